// round 1
// baseline (speedup 1.0000x reference)
#include <cuda_runtime.h>
#include <math.h>

// ---------------- problem constants (fixed by the dataset) ----------------
#define N_TOK   128        // BSZ*SEQLEN
#define N_B     32
#define N_S     4
#define N_H     16
#define D_MODEL 2048
#define D_QL    1536
#define D_QB    3072       // N_H * 192
#define D_KVL   512
#define D_NOPE  128
#define D_ROPE  64
#define D_V     128
#define D_HD    192
#define T_MAX   8192
#define T_START 8188       // MAX_SEQ - SEQLEN
#define KVPE    576        // 512 + 64
#define ATT_SCALE 0.07216878364870323f   // 192^-0.5

// ---------------- GEMM tile config ----------------
#define BM 64
#define BN 128
#define BK 16

// ---------------- scratch (static device memory: allocation-free) ----------------
__device__ float g_t1[N_TOK * D_QL];                 // x@wq_a, then rmsnormed in-place
__device__ float g_q[N_TOK * D_QB];                  // q_lora @ wq_b
__device__ float g_kvf[N_TOK * KVPE];                // x @ wkv_a
__device__ float g_kvnew[N_TOK * KVPE];              // rmsnorm(kv) ++ rope(k_pe) for new tokens
__device__ float g_qabs[N_B * 64 * KVPE];            // absorbed q (512) ++ roped q_pe (64); row = h*4+s
__device__ float g_P[16777216];                      // exp(scores) [32][64][8192]
__device__ float g_l[N_B * 64];                      // softmax denominators
__device__ float g_attn[N_B * 64 * D_KVL];           // normalized P @ kv
__device__ float g_o[N_TOK * 2048];                  // per-token concat of head outputs

// =======================================================================
// Generic NN SGEMM body: C[M,N] = A[M,K] * B[K,N], row-major.
// Block tile 64x128, BK=16, 256 threads, 4x8 per thread. M covered by blockIdx.y.
// =======================================================================
__device__ __forceinline__ void sgemm_nn_body(
    const float* __restrict__ A, int lda,
    const float* __restrict__ B, int ldb,
    float* __restrict__ C, int ldc,
    int N, int K)
{
    __shared__ float As[BK][BM];
    __shared__ float Bs[BK][BN];
    const int tid = threadIdx.x;
    const int tx = tid & 15, ty = tid >> 4;
    const int m0 = blockIdx.y * BM;
    const int n0 = blockIdx.x * BN;
    const int am = tid >> 2, ak = (tid & 3) << 2;
    const int bk = tid >> 4, bn = (tid & 15) << 3;

    float acc[4][8];
#pragma unroll
    for (int i = 0; i < 4; i++)
#pragma unroll
        for (int j = 0; j < 8; j++) acc[i][j] = 0.f;

    for (int k0 = 0; k0 < K; k0 += BK) {
        float4 av = *(const float4*)(A + (size_t)(m0 + am) * lda + k0 + ak);
        As[ak + 0][am] = av.x; As[ak + 1][am] = av.y;
        As[ak + 2][am] = av.z; As[ak + 3][am] = av.w;

        const float* bp = B + (size_t)(k0 + bk) * ldb + n0 + bn;
        if (n0 + bn + 7 < N) {
            float4 b0 = *(const float4*)bp;
            float4 b1 = *(const float4*)(bp + 4);
            *(float4*)&Bs[bk][bn]     = b0;
            *(float4*)&Bs[bk][bn + 4] = b1;
        } else {
#pragma unroll
            for (int j = 0; j < 8; j++)
                Bs[bk][bn + j] = (n0 + bn + j < N) ? bp[j] : 0.f;
        }
        __syncthreads();

#pragma unroll
        for (int kk = 0; kk < BK; kk++) {
            float a[4], bb[8];
            *(float4*)a       = *(const float4*)&As[kk][ty << 2];
            *(float4*)&bb[0]  = *(const float4*)&Bs[kk][tx << 3];
            *(float4*)&bb[4]  = *(const float4*)&Bs[kk][(tx << 3) + 4];
#pragma unroll
            for (int i = 0; i < 4; i++)
#pragma unroll
                for (int j = 0; j < 8; j++)
                    acc[i][j] = fmaf(a[i], bb[j], acc[i][j]);
        }
        __syncthreads();
    }

#pragma unroll
    for (int i = 0; i < 4; i++) {
        int m = m0 + (ty << 2) + i;
        float* cp = C + (size_t)m * ldc + n0 + (tx << 3);
#pragma unroll
        for (int j = 0; j < 8; j++)
            if (n0 + (tx << 3) + j < N) cp[j] = acc[i][j];
    }
}

// ---------------- wrappers binding scratch globals ----------------
__global__ void k_gemm_xqa(const float* __restrict__ x, const float* __restrict__ wqa) {
    sgemm_nn_body(x, D_MODEL, wqa, D_QL, g_t1, D_QL, D_QL, D_MODEL);
}
__global__ void k_gemm_qb(const float* __restrict__ wqb) {
    sgemm_nn_body(g_t1, D_QL, wqb, D_QB, g_q, D_QB, D_QB, D_QL);
}
__global__ void k_gemm_kva(const float* __restrict__ x, const float* __restrict__ wkva) {
    sgemm_nn_body(x, D_MODEL, wkva, KVPE, g_kvf, KVPE, KVPE, D_MODEL);
}
__global__ void k_gemm_wo(const float* __restrict__ wo, float* __restrict__ out) {
    sgemm_nn_body(g_o, 2048, wo, 2048, out, 2048, 2048, 2048);
}

// =======================================================================
// RMSNorm on g_t1 rows (width 1536), in place, weight qnw.
// =======================================================================
__global__ void k_rms_q(const float* __restrict__ w)
{
    const int m = blockIdx.x;
    const int tid = threadIdx.x;
    float* row = g_t1 + (size_t)m * D_QL;
    float s = 0.f;
    for (int i = tid; i < D_QL / 4; i += 256) {
        float4 v = ((const float4*)row)[i];
        s += v.x * v.x + v.y * v.y + v.z * v.z + v.w * v.w;
    }
    __shared__ float sd[256];
    sd[tid] = s; __syncthreads();
    for (int o = 128; o > 0; o >>= 1) {
        if (tid < o) sd[tid] += sd[tid + o];
        __syncthreads();
    }
    const float inv = rsqrtf(sd[0] / (float)D_QL + 1e-6f);
    for (int i = tid; i < D_QL / 4; i += 256) {
        float4 v = ((const float4*)row)[i];
        float4 wv = ((const float4*)w)[i];
        v.x *= inv * wv.x; v.y *= inv * wv.y;
        v.z *= inv * wv.z; v.w *= inv * wv.w;
        ((float4*)row)[i] = v;
    }
}

// =======================================================================
// New-token KV prep: rmsnorm first 512 of g_kvf row, rope last 64 -> g_kvnew.
// One block per token (128 threads).
// =======================================================================
__global__ void k_kvprep(const float* __restrict__ kvw,
                         const float* __restrict__ fc,
                         const float* __restrict__ fs)
{
    const int m = blockIdx.x;
    const int tid = threadIdx.x;
    const float* row = g_kvf + (size_t)m * KVPE;
    float* out = g_kvnew + (size_t)m * KVPE;

    float4 v = ((const float4*)row)[tid];   // tid*4 in [0,512)
    float s = v.x * v.x + v.y * v.y + v.z * v.z + v.w * v.w;
    __shared__ float sd[128];
    sd[tid] = s; __syncthreads();
    for (int o = 64; o > 0; o >>= 1) {
        if (tid < o) sd[tid] += sd[tid + o];
        __syncthreads();
    }
    const float inv = rsqrtf(sd[0] / (float)D_KVL + 1e-6f);
    out[tid * 4 + 0] = v.x * inv * kvw[tid * 4 + 0];
    out[tid * 4 + 1] = v.y * inv * kvw[tid * 4 + 1];
    out[tid * 4 + 2] = v.z * inv * kvw[tid * 4 + 2];
    out[tid * 4 + 3] = v.w * inv * kvw[tid * 4 + 3];

    if (tid < 32) {
        const int sidx = m & 3;
        const float c = fc[sidx * 32 + tid], sn = fs[sidx * 32 + tid];
        const float x0 = row[512 + 2 * tid], x1 = row[512 + 2 * tid + 1];
        out[512 + 2 * tid]     = x0 * c - x1 * sn;
        out[512 + 2 * tid + 1] = x0 * sn + x1 * c;
    }
}

// =======================================================================
// Absorb: q_abs[b][h*4+s][c] = sum_d q[b,s,h*192+d] * wkv_b[h*256+d][c], c<512.
// Per-head NN GEMM: M=128 tokens, N=512, K=128. grid (4, 2, 16).
// =======================================================================
__global__ void k_absorb(const float* __restrict__ wkvb)
{
    __shared__ float As[BK][BM];
    __shared__ float Bs[BK][BN];
    const int h = blockIdx.z;
    const int tid = threadIdx.x;
    const int tx = tid & 15, ty = tid >> 4;
    const int m0 = blockIdx.y * BM;
    const int n0 = blockIdx.x * BN;
    const int am = tid >> 2, ak = (tid & 3) << 2;
    const int bk = tid >> 4, bn = (tid & 15) << 3;

    const float* A = g_q + h * D_HD;                    // lda = 3072
    const float* B = wkvb + (size_t)(h * 256) * D_KVL;  // ldb = 512

    float acc[4][8];
#pragma unroll
    for (int i = 0; i < 4; i++)
#pragma unroll
        for (int j = 0; j < 8; j++) acc[i][j] = 0.f;

    for (int k0 = 0; k0 < D_NOPE; k0 += BK) {
        float4 av = *(const float4*)(A + (size_t)(m0 + am) * D_QB + k0 + ak);
        As[ak + 0][am] = av.x; As[ak + 1][am] = av.y;
        As[ak + 2][am] = av.z; As[ak + 3][am] = av.w;
        const float* bp = B + (size_t)(k0 + bk) * D_KVL + n0 + bn;
        *(float4*)&Bs[bk][bn]     = *(const float4*)bp;
        *(float4*)&Bs[bk][bn + 4] = *(const float4*)(bp + 4);
        __syncthreads();
#pragma unroll
        for (int kk = 0; kk < BK; kk++) {
            float a[4], bb[8];
            *(float4*)a      = *(const float4*)&As[kk][ty << 2];
            *(float4*)&bb[0] = *(const float4*)&Bs[kk][tx << 3];
            *(float4*)&bb[4] = *(const float4*)&Bs[kk][(tx << 3) + 4];
#pragma unroll
            for (int i = 0; i < 4; i++)
#pragma unroll
                for (int j = 0; j < 8; j++)
                    acc[i][j] = fmaf(a[i], bb[j], acc[i][j]);
        }
        __syncthreads();
    }
#pragma unroll
    for (int i = 0; i < 4; i++) {
        const int m = m0 + (ty << 2) + i;
        const int row = (m >> 2) * 64 + h * 4 + (m & 3);
        float* cp = g_qabs + (size_t)row * KVPE + n0 + (tx << 3);
#pragma unroll
        for (int j = 0; j < 8; j++) cp[j] = acc[i][j];
    }
}

// =======================================================================
// Rope q_pe into g_qabs[..., 512:576]. 65536 pair work items.
// =======================================================================
__global__ void k_qrope(const float* __restrict__ fc, const float* __restrict__ fs)
{
    const int idx = blockIdx.x * blockDim.x + threadIdx.x;   // < 128*16*32
    const int j = idx & 31;
    const int h = (idx >> 5) & 15;
    const int m = idx >> 9;
    const int s = m & 3;
    const float c = fc[s * 32 + j], sn = fs[s * 32 + j];
    const float* src = g_q + (size_t)m * D_QB + h * D_HD + D_NOPE + 2 * j;
    const float x0 = src[0], x1 = src[1];
    const int row = (m >> 2) * 64 + h * 4 + s;
    float* dst = g_qabs + (size_t)row * KVPE + 512 + 2 * j;
    dst[0] = x0 * c - x1 * sn;
    dst[1] = x0 * sn + x1 * c;
}

// =======================================================================
// Scores (pass A): P[b][r][t] = exp(scale * <q_abs[b][r], kvpe[b][t]>).
// NT GEMM: M=64 rows, tile N=128 t, K=576. grid (64 ttiles, 32 b).
// Last 4 t come from g_kvnew. No max-subtraction: logits bounded (~|z|<6).
// =======================================================================
__global__ void k_scores(const float* __restrict__ kvc, const float* __restrict__ pec)
{
    __shared__ float As[BK][BM];
    __shared__ float Bs[BK][BN];
    const int tid = threadIdx.x;
    const int tx = tid & 15, ty = tid >> 4;
    const int b = blockIdx.y;
    const int t0 = blockIdx.x * BN;
    const float* A = g_qabs + (size_t)b * 64 * KVPE;
    const int am = tid >> 2, ak = (tid & 3) << 2;
    const int bt = tid >> 1, bkq = (tid & 1) << 3;
    const int tglob = t0 + bt;

    float acc[4][8];
#pragma unroll
    for (int i = 0; i < 4; i++)
#pragma unroll
        for (int j = 0; j < 8; j++) acc[i][j] = 0.f;

    for (int k0 = 0; k0 < KVPE; k0 += BK) {
        float4 av = *(const float4*)(A + (size_t)am * KVPE + k0 + ak);
        As[ak + 0][am] = av.x; As[ak + 1][am] = av.y;
        As[ak + 2][am] = av.z; As[ak + 3][am] = av.w;

        const float* p;
        if (tglob >= T_START)
            p = g_kvnew + (size_t)(b * N_S + tglob - T_START) * KVPE + k0 + bkq;
        else if (k0 < D_KVL)
            p = kvc + ((size_t)b * T_MAX + tglob) * D_KVL + k0 + bkq;
        else
            p = pec + ((size_t)b * T_MAX + tglob) * D_ROPE + (k0 - D_KVL) + bkq;
        float4 b0 = *(const float4*)p;
        float4 b1 = *(const float4*)(p + 4);
        Bs[bkq + 0][bt] = b0.x; Bs[bkq + 1][bt] = b0.y;
        Bs[bkq + 2][bt] = b0.z; Bs[bkq + 3][bt] = b0.w;
        Bs[bkq + 4][bt] = b1.x; Bs[bkq + 5][bt] = b1.y;
        Bs[bkq + 6][bt] = b1.z; Bs[bkq + 7][bt] = b1.w;
        __syncthreads();

#pragma unroll
        for (int kk = 0; kk < BK; kk++) {
            float a[4], bb[8];
            *(float4*)a      = *(const float4*)&As[kk][ty << 2];
            *(float4*)&bb[0] = *(const float4*)&Bs[kk][tx << 3];
            *(float4*)&bb[4] = *(const float4*)&Bs[kk][(tx << 3) + 4];
#pragma unroll
            for (int i = 0; i < 4; i++)
#pragma unroll
                for (int j = 0; j < 8; j++)
                    acc[i][j] = fmaf(a[i], bb[j], acc[i][j]);
        }
        __syncthreads();
    }

#pragma unroll
    for (int i = 0; i < 4; i++) {
        const int r = (ty << 2) + i;
        float* dst = g_P + ((size_t)b * 64 + r) * T_MAX + t0 + (tx << 3);
        float4 o0, o1;
        o0.x = __expf(acc[i][0] * ATT_SCALE); o0.y = __expf(acc[i][1] * ATT_SCALE);
        o0.z = __expf(acc[i][2] * ATT_SCALE); o0.w = __expf(acc[i][3] * ATT_SCALE);
        o1.x = __expf(acc[i][4] * ATT_SCALE); o1.y = __expf(acc[i][5] * ATT_SCALE);
        o1.z = __expf(acc[i][6] * ATT_SCALE); o1.w = __expf(acc[i][7] * ATT_SCALE);
        *(float4*)dst       = o0;
        *(float4*)(dst + 4) = o1;
    }
}

// =======================================================================
// Deterministic row sums of P -> g_l. One block per (r, b).
// =======================================================================
__global__ void k_rowsum()
{
    const int r = blockIdx.x, b = blockIdx.y;
    const float* p = g_P + ((size_t)b * 64 + r) * T_MAX;
    float s = 0.f;
    for (int i = threadIdx.x; i < T_MAX / 4; i += 256) {
        float4 v = ((const float4*)p)[i];
        s += v.x + v.y + v.z + v.w;
    }
    __shared__ float sd[256];
    sd[threadIdx.x] = s; __syncthreads();
    for (int o = 128; o > 0; o >>= 1) {
        if (threadIdx.x < o) sd[threadIdx.x] += sd[threadIdx.x + o];
        __syncthreads();
    }
    if (threadIdx.x == 0) g_l[b * 64 + r] = sd[0];
}

// =======================================================================
// Attention output (pass C): attn[b][r][c] = (P[b][r] @ kv[b][:,c]) / l[b][r].
// NN GEMM M=64, N=512 (4 tiles), K=8192. grid (4, 32).
// =======================================================================
__global__ void k_attnout(const float* __restrict__ kvc)
{
    __shared__ float As[BK][BM];
    __shared__ float Bs[BK][BN];
    const int tid = threadIdx.x;
    const int tx = tid & 15, ty = tid >> 4;
    const int b = blockIdx.y;
    const int n0 = blockIdx.x * BN;
    const float* A = g_P + (size_t)b * 64 * T_MAX;
    const int am = tid >> 2, ak = (tid & 3) << 2;
    const int bk = tid >> 4, bn = (tid & 15) << 3;

    float acc[4][8];
#pragma unroll
    for (int i = 0; i < 4; i++)
#pragma unroll
        for (int j = 0; j < 8; j++) acc[i][j] = 0.f;

    for (int k0 = 0; k0 < T_MAX; k0 += BK) {
        float4 av = *(const float4*)(A + (size_t)am * T_MAX + k0 + ak);
        As[ak + 0][am] = av.x; As[ak + 1][am] = av.y;
        As[ak + 2][am] = av.z; As[ak + 3][am] = av.w;
        const int t = k0 + bk;
        const float* bp = (t >= T_START)
            ? g_kvnew + (size_t)(b * N_S + t - T_START) * KVPE + n0 + bn
            : kvc + ((size_t)b * T_MAX + t) * D_KVL + n0 + bn;
        *(float4*)&Bs[bk][bn]     = *(const float4*)bp;
        *(float4*)&Bs[bk][bn + 4] = *(const float4*)(bp + 4);
        __syncthreads();
#pragma unroll
        for (int kk = 0; kk < BK; kk++) {
            float a[4], bb[8];
            *(float4*)a      = *(const float4*)&As[kk][ty << 2];
            *(float4*)&bb[0] = *(const float4*)&Bs[kk][tx << 3];
            *(float4*)&bb[4] = *(const float4*)&Bs[kk][(tx << 3) + 4];
#pragma unroll
            for (int i = 0; i < 4; i++)
#pragma unroll
                for (int j = 0; j < 8; j++)
                    acc[i][j] = fmaf(a[i], bb[j], acc[i][j]);
        }
        __syncthreads();
    }

#pragma unroll
    for (int i = 0; i < 4; i++) {
        const int r = (ty << 2) + i;
        const float rl = 1.0f / g_l[b * 64 + r];
        float* cp = g_attn + ((size_t)b * 64 + r) * D_KVL + n0 + (tx << 3);
#pragma unroll
        for (int j = 0; j < 8; j++) cp[j] = acc[i][j] * rl;
    }
}

// =======================================================================
// V projection: o[m][h*128+v] = sum_c attn[b][h*4+s][c] * wkv_b[h*256+128+v][c].
// NT GEMM per head: M=128 tokens, N=128, K=512. grid (1, 2, 16).
// =======================================================================
__global__ void k_projv(const float* __restrict__ wkvb)
{
    __shared__ float As[BK][BM];
    __shared__ float Bs[BK][BN];
    const int h = blockIdx.z;
    const int tid = threadIdx.x;
    const int tx = tid & 15, ty = tid >> 4;
    const int m0 = blockIdx.y * BM;
    const int am = tid >> 2, ak = (tid & 3) << 2;
    const int bt = tid >> 1, bkq = (tid & 1) << 3;

    const int lm = m0 + am;
    const int arow = (lm >> 2) * 64 + h * 4 + (lm & 3);
    const float* arp = g_attn + (size_t)arow * D_KVL;
    const float* brp = wkvb + (size_t)(h * 256 + 128 + bt) * D_KVL;

    float acc[4][8];
#pragma unroll
    for (int i = 0; i < 4; i++)
#pragma unroll
        for (int j = 0; j < 8; j++) acc[i][j] = 0.f;

    for (int k0 = 0; k0 < D_KVL; k0 += BK) {
        float4 av = *(const float4*)(arp + k0 + ak);
        As[ak + 0][am] = av.x; As[ak + 1][am] = av.y;
        As[ak + 2][am] = av.z; As[ak + 3][am] = av.w;
        float4 b0 = *(const float4*)(brp + k0 + bkq);
        float4 b1 = *(const float4*)(brp + k0 + bkq + 4);
        Bs[bkq + 0][bt] = b0.x; Bs[bkq + 1][bt] = b0.y;
        Bs[bkq + 2][bt] = b0.z; Bs[bkq + 3][bt] = b0.w;
        Bs[bkq + 4][bt] = b1.x; Bs[bkq + 5][bt] = b1.y;
        Bs[bkq + 6][bt] = b1.z; Bs[bkq + 7][bt] = b1.w;
        __syncthreads();
#pragma unroll
        for (int kk = 0; kk < BK; kk++) {
            float a[4], bb[8];
            *(float4*)a      = *(const float4*)&As[kk][ty << 2];
            *(float4*)&bb[0] = *(const float4*)&Bs[kk][tx << 3];
            *(float4*)&bb[4] = *(const float4*)&Bs[kk][(tx << 3) + 4];
#pragma unroll
            for (int i = 0; i < 4; i++)
#pragma unroll
                for (int j = 0; j < 8; j++)
                    acc[i][j] = fmaf(a[i], bb[j], acc[i][j]);
        }
        __syncthreads();
    }
#pragma unroll
    for (int i = 0; i < 4; i++) {
        const int m = m0 + (ty << 2) + i;
        float* cp = g_o + (size_t)m * 2048 + h * D_V + (tx << 3);
#pragma unroll
        for (int j = 0; j < 8; j++) cp[j] = acc[i][j];
    }
}

// =======================================================================
// launch
// =======================================================================
extern "C" void kernel_launch(void* const* d_in, const int* in_sizes, int n_in,
                              void* d_out, int out_size)
{
    (void)in_sizes; (void)n_in; (void)out_size;
    const float* x     = (const float*)d_in[0];
    const float* wq_a  = (const float*)d_in[1];
    const float* qnw   = (const float*)d_in[2];
    const float* wq_b  = (const float*)d_in[3];
    const float* wkv_a = (const float*)d_in[4];
    const float* kvnw  = (const float*)d_in[5];
    const float* wkv_b = (const float*)d_in[6];
    const float* wo    = (const float*)d_in[7];
    const float* kvc   = (const float*)d_in[8];
    const float* pec   = (const float*)d_in[9];
    const float* fc    = (const float*)d_in[10];
    const float* fs    = (const float*)d_in[11];
    float* out = (float*)d_out;

    k_gemm_xqa<<<dim3(D_QL / BN, 2), 256>>>(x, wq_a);
    k_rms_q<<<N_TOK, 256>>>(qnw);
    k_gemm_qb<<<dim3(D_QB / BN, 2), 256>>>(wq_b);
    k_gemm_kva<<<dim3((KVPE + BN - 1) / BN, 2), 256>>>(x, wkv_a);
    k_kvprep<<<N_TOK, 128>>>(kvnw, fc, fs);
    k_absorb<<<dim3(D_KVL / BN, 2, N_H), 256>>>(wkv_b);
    k_qrope<<<256, 256>>>(fc, fs);
    k_scores<<<dim3(T_MAX / BN, N_B), 256>>>(kvc, pec);
    k_rowsum<<<dim3(64, N_B), 256>>>();
    k_attnout<<<dim3(D_KVL / BN, N_B), 256>>>(kvc);
    k_projv<<<dim3(1, 2, N_H), 256>>>(wkv_b);
    k_gemm_wo<<<dim3(2048 / BN, 2), 256>>>(wo, out);
}

// round 3
// speedup vs baseline: 1.8301x; 1.8301x over previous
#include <cuda_runtime.h>
#include <cuda_bf16.h>
#include <math.h>
#include <stdint.h>

// ---------------- problem constants ----------------
#define N_TOK   128
#define N_B     32
#define N_S     4
#define N_H     16
#define D_MODEL 2048
#define D_QL    1536
#define D_QB    3072
#define D_KVL   512
#define D_NOPE  128
#define D_ROPE  64
#define D_V     128
#define D_HD    192
#define T_MAX   8192
#define T_START 8188
#define KVPE    576
#define ATT_SCALE 0.07216878364870323f

#define BM 64
#define BN 128
#define BK 16
#define SROWP 20          // smem row stride (bf16 units) for 16-wide k chunks

// ---------------- static scratch ----------------
__device__ float g_t1[N_TOK * D_QL];
__device__ float g_q[N_TOK * D_QB];
__device__ float g_kvf[N_TOK * KVPE];
__device__ float g_kvnew[N_TOK * KVPE];
__device__ float g_qabs[N_B * 64 * KVPE];
__device__ __nv_bfloat16 g_qh[N_B * 64 * KVPE];
__device__ __nv_bfloat16 g_ql[N_B * 64 * KVPE];
__device__ __nv_bfloat16 g_Ph[(size_t)N_B * 64 * T_MAX];
__device__ __nv_bfloat16 g_Pl[(size_t)N_B * 64 * T_MAX];
__device__ float g_l[N_B * 64];
__device__ float g_part[(size_t)N_B * 8 * 64 * D_KVL];
__device__ float g_attn[N_B * 64 * D_KVL];
__device__ float g_o[N_TOK * 2048];
__device__ float g_red[2200000];          // split-K partials (max 8*128*2048)

// ---------------- helpers ----------------
__device__ __forceinline__ uint32_t packbf2(__nv_bfloat16 a, __nv_bfloat16 b) {
    __nv_bfloat162 t = __halves2bfloat162(a, b);
    return *reinterpret_cast<uint32_t*>(&t);
}
__device__ __forceinline__ void split2(float a, float b, uint32_t& h, uint32_t& l) {
    __nv_bfloat16 ah = __float2bfloat16(a);
    __nv_bfloat16 bh = __float2bfloat16(b);
    __nv_bfloat16 al = __float2bfloat16(a - __bfloat162float(ah));
    __nv_bfloat16 bl = __float2bfloat16(b - __bfloat162float(bh));
    h = packbf2(ah, bh);
    l = packbf2(al, bl);
}
__device__ __forceinline__ void mma_bf16(float* c, const uint32_t* a, uint32_t b0, uint32_t b1) {
    asm volatile(
        "mma.sync.aligned.m16n8k16.row.col.f32.bf16.bf16.f32 "
        "{%0,%1,%2,%3}, {%4,%5,%6,%7}, {%8,%9}, {%0,%1,%2,%3};\n"
        : "+f"(c[0]), "+f"(c[1]), "+f"(c[2]), "+f"(c[3])
        : "r"(a[0]), "r"(a[1]), "r"(a[2]), "r"(a[3]), "r"(b0), "r"(b1));
}

// =======================================================================
// fp32 SGEMM NN body with K-range (for split-K). Tile 64x128, 256 thr.
// =======================================================================
__device__ __forceinline__ void sgemm_nn_body(
    const float* __restrict__ A, int lda,
    const float* __restrict__ B, int ldb,
    float* __restrict__ C, int ldc,
    int N, int kbeg, int kend)
{
    __shared__ float As[BK][BM];
    __shared__ float Bs[BK][BN];
    const int tid = threadIdx.x;
    const int tx = tid & 15, ty = tid >> 4;
    const int m0 = blockIdx.y * BM;
    const int n0 = blockIdx.x * BN;
    const int am = tid >> 2, ak = (tid & 3) << 2;
    const int bkr = tid >> 4, bn = (tid & 15) << 3;

    float acc[4][8];
#pragma unroll
    for (int i = 0; i < 4; i++)
#pragma unroll
        for (int j = 0; j < 8; j++) acc[i][j] = 0.f;

    for (int k0 = kbeg; k0 < kend; k0 += BK) {
        float4 av = *(const float4*)(A + (size_t)(m0 + am) * lda + k0 + ak);
        As[ak + 0][am] = av.x; As[ak + 1][am] = av.y;
        As[ak + 2][am] = av.z; As[ak + 3][am] = av.w;
        const float* bp = B + (size_t)(k0 + bkr) * ldb + n0 + bn;
        if (n0 + bn + 7 < N) {
            *(float4*)&Bs[bkr][bn]     = *(const float4*)bp;
            *(float4*)&Bs[bkr][bn + 4] = *(const float4*)(bp + 4);
        } else {
#pragma unroll
            for (int j = 0; j < 8; j++)
                Bs[bkr][bn + j] = (n0 + bn + j < N) ? bp[j] : 0.f;
        }
        __syncthreads();
#pragma unroll
        for (int kk = 0; kk < BK; kk++) {
            float a[4], bb[8];
            *(float4*)a      = *(const float4*)&As[kk][ty << 2];
            *(float4*)&bb[0] = *(const float4*)&Bs[kk][tx << 3];
            *(float4*)&bb[4] = *(const float4*)&Bs[kk][(tx << 3) + 4];
#pragma unroll
            for (int i = 0; i < 4; i++)
#pragma unroll
                for (int j = 0; j < 8; j++)
                    acc[i][j] = fmaf(a[i], bb[j], acc[i][j]);
        }
        __syncthreads();
    }
#pragma unroll
    for (int i = 0; i < 4; i++) {
        int m = m0 + (ty << 2) + i;
        float* cp = C + (size_t)m * ldc + n0 + (tx << 3);
#pragma unroll
        for (int j = 0; j < 8; j++)
            if (n0 + (tx << 3) + j < N) cp[j] = acc[i][j];
    }
}

// ---------------- split-K GEMM wrappers ----------------
__global__ void k_sgemm_xqa(const float* __restrict__ x, const float* __restrict__ w) {
    const int z = blockIdx.z, ks = D_MODEL / 8;
    sgemm_nn_body(x, D_MODEL, w, D_QL, g_red + (size_t)z * N_TOK * D_QL, D_QL,
                  D_QL, z * ks, (z + 1) * ks);
}
__global__ void k_sgemm_qb(const float* __restrict__ w) {
    const int z = blockIdx.z, ks = D_QL / 4;
    sgemm_nn_body(g_t1, D_QL, w, D_QB, g_red + (size_t)z * N_TOK * D_QB, D_QB,
                  D_QB, z * ks, (z + 1) * ks);
}
__global__ void k_sgemm_kva(const float* __restrict__ x, const float* __restrict__ w) {
    const int z = blockIdx.z, ks = D_MODEL / 16;
    sgemm_nn_body(x, D_MODEL, w, KVPE, g_red + (size_t)z * N_TOK * KVPE, KVPE,
                  KVPE, z * ks, (z + 1) * ks);
}
__global__ void k_sgemm_wo(const float* __restrict__ w) {
    const int z = blockIdx.z, ks = 2048 / 8;
    sgemm_nn_body(g_o, 2048, w, 2048, g_red + (size_t)z * N_TOK * 2048, 2048,
                  2048, z * ks, (z + 1) * ks);
}

// ---------------- reduce wrappers ----------------
__device__ __forceinline__ void reduce_body(const float* __restrict__ src,
                                            float* __restrict__ dst, int mn, int splits) {
    int i = blockIdx.x * 256 + threadIdx.x;
    if (i >= mn) return;
    float s = 0.f;
    for (int k = 0; k < splits; k++) s += src[i + (size_t)k * mn];
    dst[i] = s;
}
__global__ void k_red_t1()  { reduce_body(g_red, g_t1,  N_TOK * D_QL, 8); }
__global__ void k_red_q()   { reduce_body(g_red, g_q,   N_TOK * D_QB, 4); }
__global__ void k_red_kvf() { reduce_body(g_red, g_kvf, N_TOK * KVPE, 16); }
__global__ void k_red_o()   { reduce_body(g_red, g_o,   N_TOK * 2048, 4); }
__global__ void k_red_out(float* __restrict__ out) { reduce_body(g_red, out, N_TOK * 2048, 8); }

// =======================================================================
// RMSNorm q_lora rows (1536)
// =======================================================================
__global__ void k_rms_q(const float* __restrict__ w)
{
    const int m = blockIdx.x, tid = threadIdx.x;
    float* row = g_t1 + (size_t)m * D_QL;
    float s = 0.f;
    for (int i = tid; i < D_QL / 4; i += 256) {
        float4 v = ((const float4*)row)[i];
        s += v.x * v.x + v.y * v.y + v.z * v.z + v.w * v.w;
    }
    __shared__ float sd[256];
    sd[tid] = s; __syncthreads();
    for (int o = 128; o > 0; o >>= 1) {
        if (tid < o) sd[tid] += sd[tid + o];
        __syncthreads();
    }
    const float inv = rsqrtf(sd[0] / (float)D_QL + 1e-6f);
    for (int i = tid; i < D_QL / 4; i += 256) {
        float4 v = ((const float4*)row)[i];
        float4 wv = ((const float4*)w)[i];
        v.x *= inv * wv.x; v.y *= inv * wv.y;
        v.z *= inv * wv.z; v.w *= inv * wv.w;
        ((float4*)row)[i] = v;
    }
}

// =======================================================================
// KV prep for the 4 new tokens per batch
// =======================================================================
__global__ void k_kvprep(const float* __restrict__ kvw,
                         const float* __restrict__ fc,
                         const float* __restrict__ fs)
{
    const int m = blockIdx.x, tid = threadIdx.x;
    const float* row = g_kvf + (size_t)m * KVPE;
    float* out = g_kvnew + (size_t)m * KVPE;
    float4 v = ((const float4*)row)[tid];
    float s = v.x * v.x + v.y * v.y + v.z * v.z + v.w * v.w;
    __shared__ float sd[128];
    sd[tid] = s; __syncthreads();
    for (int o = 64; o > 0; o >>= 1) {
        if (tid < o) sd[tid] += sd[tid + o];
        __syncthreads();
    }
    const float inv = rsqrtf(sd[0] / (float)D_KVL + 1e-6f);
    out[tid * 4 + 0] = v.x * inv * kvw[tid * 4 + 0];
    out[tid * 4 + 1] = v.y * inv * kvw[tid * 4 + 1];
    out[tid * 4 + 2] = v.z * inv * kvw[tid * 4 + 2];
    out[tid * 4 + 3] = v.w * inv * kvw[tid * 4 + 3];
    if (tid < 32) {
        const int sidx = m & 3;
        const float c = fc[sidx * 32 + tid], sn = fs[sidx * 32 + tid];
        const float x0 = row[512 + 2 * tid], x1 = row[512 + 2 * tid + 1];
        out[512 + 2 * tid]     = x0 * c - x1 * sn;
        out[512 + 2 * tid + 1] = x0 * sn + x1 * c;
    }
}

// =======================================================================
// Absorb q_nope through wkv_b[:, :128, :] -> g_qabs[:, :512]
// =======================================================================
__global__ void k_absorb(const float* __restrict__ wkvb)
{
    __shared__ float As[BK][BM];
    __shared__ float Bs[BK][BN];
    const int h = blockIdx.z, tid = threadIdx.x;
    const int tx = tid & 15, ty = tid >> 4;
    const int m0 = blockIdx.y * BM, n0 = blockIdx.x * BN;
    const int am = tid >> 2, ak = (tid & 3) << 2;
    const int bkr = tid >> 4, bn = (tid & 15) << 3;
    const float* A = g_q + h * D_HD;
    const float* B = wkvb + (size_t)(h * 256) * D_KVL;
    float acc[4][8];
#pragma unroll
    for (int i = 0; i < 4; i++)
#pragma unroll
        for (int j = 0; j < 8; j++) acc[i][j] = 0.f;
    for (int k0 = 0; k0 < D_NOPE; k0 += BK) {
        float4 av = *(const float4*)(A + (size_t)(m0 + am) * D_QB + k0 + ak);
        As[ak + 0][am] = av.x; As[ak + 1][am] = av.y;
        As[ak + 2][am] = av.z; As[ak + 3][am] = av.w;
        const float* bp = B + (size_t)(k0 + bkr) * D_KVL + n0 + bn;
        *(float4*)&Bs[bkr][bn]     = *(const float4*)bp;
        *(float4*)&Bs[bkr][bn + 4] = *(const float4*)(bp + 4);
        __syncthreads();
#pragma unroll
        for (int kk = 0; kk < BK; kk++) {
            float a[4], bb[8];
            *(float4*)a      = *(const float4*)&As[kk][ty << 2];
            *(float4*)&bb[0] = *(const float4*)&Bs[kk][tx << 3];
            *(float4*)&bb[4] = *(const float4*)&Bs[kk][(tx << 3) + 4];
#pragma unroll
            for (int i = 0; i < 4; i++)
#pragma unroll
                for (int j = 0; j < 8; j++)
                    acc[i][j] = fmaf(a[i], bb[j], acc[i][j]);
        }
        __syncthreads();
    }
#pragma unroll
    for (int i = 0; i < 4; i++) {
        const int m = m0 + (ty << 2) + i;
        const int row = (m >> 2) * 64 + h * 4 + (m & 3);
        float* cp = g_qabs + (size_t)row * KVPE + n0 + (tx << 3);
#pragma unroll
        for (int j = 0; j < 8; j++) cp[j] = acc[i][j];
    }
}

// =======================================================================
// Rope q_pe -> g_qabs[..., 512:576]
// =======================================================================
__global__ void k_qrope(const float* __restrict__ fc, const float* __restrict__ fs)
{
    const int idx = blockIdx.x * blockDim.x + threadIdx.x;
    const int j = idx & 31, h = (idx >> 5) & 15, m = idx >> 9, s = m & 3;
    const float c = fc[s * 32 + j], sn = fs[s * 32 + j];
    const float* src = g_q + (size_t)m * D_QB + h * D_HD + D_NOPE + 2 * j;
    const float x0 = src[0], x1 = src[1];
    const int row = (m >> 2) * 64 + h * 4 + s;
    float* dst = g_qabs + (size_t)row * KVPE + 512 + 2 * j;
    dst[0] = x0 * c - x1 * sn;
    dst[1] = x0 * sn + x1 * c;
}

// =======================================================================
// Split g_qabs fp32 -> bf16 hi/lo
// =======================================================================
__global__ void k_qsplit()
{
    const int i = blockIdx.x * 256 + threadIdx.x;
    if (i >= N_B * 64 * KVPE) return;
    float v = g_qabs[i];
    __nv_bfloat16 h = __float2bfloat16(v);
    g_qh[i] = h;
    g_ql[i] = __float2bfloat16(v - __bfloat162float(h));
}

// =======================================================================
// Scores via mma.sync bf16 split: P = exp(scale * Q' KV^T), stored hi/lo bf16.
// Block: 64 q-rows x 256 tokens, K=576.  8 warps = 2(m) x 4(t), warp 32x64.
// grid (32 t-tiles, 32 b), 256 threads.
// =======================================================================
__global__ __launch_bounds__(256) void k_scores_mma(const float* __restrict__ kvc,
                                                    const float* __restrict__ pec)
{
    __shared__ __nv_bfloat16 Qh[64 * SROWP], Ql[64 * SROWP];
    __shared__ __nv_bfloat16 Kh[256 * SROWP], Kl[256 * SROWP];

    const int tid = threadIdx.x;
    const int lane = tid & 31, w = tid >> 5;
    const int wm = w & 1, wt = w >> 1;
    const int b = blockIdx.y;
    const int t0 = blockIdx.x * 256;

    float acc[2][8][4];
#pragma unroll
    for (int mi = 0; mi < 2; mi++)
#pragma unroll
        for (int ni = 0; ni < 8; ni++)
#pragma unroll
            for (int q = 0; q < 4; q++) acc[mi][ni][q] = 0.f;

    const int qrow = tid >> 2, qq = (tid & 3) * 4;
    const int kt = tid;
    const int tg = t0 + kt;
    const float* rowkv;
    const float* rowpe;
    if (tg >= T_START) {
        rowkv = g_kvnew + (size_t)(b * N_S + tg - T_START) * KVPE;
        rowpe = rowkv + 512;
    } else {
        rowkv = kvc + ((size_t)b * T_MAX + tg) * D_KVL;
        rowpe = pec + ((size_t)b * T_MAX + tg) * D_ROPE;
    }
    const __nv_bfloat16* qhp = g_qh + ((size_t)b * 64 + qrow) * KVPE + qq;
    const __nv_bfloat16* qlp = g_ql + ((size_t)b * 64 + qrow) * KVPE + qq;

    const int lr = lane >> 2;
    const int lk = (lane & 3) * 2;

    for (int k0 = 0; k0 < KVPE; k0 += 16) {
        __syncthreads();
        *(uint64_t*)&Qh[qrow * SROWP + qq] = *(const uint64_t*)(qhp + k0);
        *(uint64_t*)&Ql[qrow * SROWP + qq] = *(const uint64_t*)(qlp + k0);
        const float* src = (k0 < D_KVL) ? rowkv + k0 : rowpe + (k0 - D_KVL);
#pragma unroll
        for (int j = 0; j < 16; j += 4) {
            float4 v = *(const float4*)(src + j);
            uint32_t h0, l0, h1, l1;
            split2(v.x, v.y, h0, l0);
            split2(v.z, v.w, h1, l1);
            *(uint32_t*)&Kh[kt * SROWP + j]     = h0;
            *(uint32_t*)&Kh[kt * SROWP + j + 2] = h1;
            *(uint32_t*)&Kl[kt * SROWP + j]     = l0;
            *(uint32_t*)&Kl[kt * SROWP + j + 2] = l1;
        }
        __syncthreads();

        uint32_t ah[2][4], al[2][4];
#pragma unroll
        for (int mi = 0; mi < 2; mi++) {
            const int R = wm * 32 + mi * 16 + lr;
            ah[mi][0] = *(uint32_t*)&Qh[R * SROWP + lk];
            ah[mi][1] = *(uint32_t*)&Qh[(R + 8) * SROWP + lk];
            ah[mi][2] = *(uint32_t*)&Qh[R * SROWP + lk + 8];
            ah[mi][3] = *(uint32_t*)&Qh[(R + 8) * SROWP + lk + 8];
            al[mi][0] = *(uint32_t*)&Ql[R * SROWP + lk];
            al[mi][1] = *(uint32_t*)&Ql[(R + 8) * SROWP + lk];
            al[mi][2] = *(uint32_t*)&Ql[R * SROWP + lk + 8];
            al[mi][3] = *(uint32_t*)&Ql[(R + 8) * SROWP + lk + 8];
        }
#pragma unroll
        for (int ni = 0; ni < 8; ni++) {
            const int T = wt * 64 + ni * 8 + lr;
            uint32_t bh0 = *(uint32_t*)&Kh[T * SROWP + lk];
            uint32_t bh1 = *(uint32_t*)&Kh[T * SROWP + lk + 8];
            uint32_t bl0 = *(uint32_t*)&Kl[T * SROWP + lk];
            uint32_t bl1 = *(uint32_t*)&Kl[T * SROWP + lk + 8];
#pragma unroll
            for (int mi = 0; mi < 2; mi++) {
                mma_bf16(acc[mi][ni], ah[mi], bh0, bh1);
                mma_bf16(acc[mi][ni], ah[mi], bl0, bl1);
                mma_bf16(acc[mi][ni], al[mi], bh0, bh1);
            }
        }
    }

#pragma unroll
    for (int mi = 0; mi < 2; mi++) {
#pragma unroll
        for (int ni = 0; ni < 8; ni++) {
            const int r = wm * 32 + mi * 16 + lr;
            const int t = t0 + wt * 64 + ni * 8 + lk;
            size_t base = ((size_t)b * 64 + r) * T_MAX + t;
            float e0 = __expf(acc[mi][ni][0] * ATT_SCALE);
            float e1 = __expf(acc[mi][ni][1] * ATT_SCALE);
            float e2 = __expf(acc[mi][ni][2] * ATT_SCALE);
            float e3 = __expf(acc[mi][ni][3] * ATT_SCALE);
            uint32_t h, l;
            split2(e0, e1, h, l);
            *(uint32_t*)&g_Ph[base] = h;
            *(uint32_t*)&g_Pl[base] = l;
            split2(e2, e3, h, l);
            *(uint32_t*)&g_Ph[base + (size_t)8 * T_MAX] = h;
            *(uint32_t*)&g_Pl[base + (size_t)8 * T_MAX] = l;
        }
    }
}

// =======================================================================
// Row sums of P (hi+lo) -> g_l
// =======================================================================
__global__ void k_rowsum()
{
    const int r = blockIdx.x, b = blockIdx.y, tid = threadIdx.x;
    const __nv_bfloat162* ph = (const __nv_bfloat162*)(g_Ph + ((size_t)b * 64 + r) * T_MAX);
    const __nv_bfloat162* pl = (const __nv_bfloat162*)(g_Pl + ((size_t)b * 64 + r) * T_MAX);
    float s = 0.f;
    for (int i = tid; i < T_MAX / 2; i += 256) {
        float2 h = __bfloat1622float2(ph[i]);
        float2 l = __bfloat1622float2(pl[i]);
        s += h.x + h.y + l.x + l.y;
    }
    __shared__ float sd[256];
    sd[tid] = s; __syncthreads();
    for (int o = 128; o > 0; o >>= 1) {
        if (tid < o) sd[tid] += sd[tid + o];
        __syncthreads();
    }
    if (tid == 0) g_l[b * 64 + r] = sd[0];
}

// =======================================================================
// Attention out via mma.sync bf16 split over 1024-token slices.
// grid (2 c-tiles, 8 splits, 32 b).
// =======================================================================
__global__ __launch_bounds__(256) void k_attnout_mma(const float* __restrict__ kvc)
{
    __shared__ __nv_bfloat16 Ah[64 * SROWP], Al[64 * SROWP];
    __shared__ __nv_bfloat16 Bh[256 * SROWP], Bl[256 * SROWP];

    const int tid = threadIdx.x;
    const int lane = tid & 31, w = tid >> 5;
    const int wm = w & 1, wc = w >> 1;
    const int c0 = blockIdx.x * 256;
    const int split = blockIdx.y;
    const int b = blockIdx.z;

    float acc[2][8][4];
#pragma unroll
    for (int mi = 0; mi < 2; mi++)
#pragma unroll
        for (int ni = 0; ni < 8; ni++)
#pragma unroll
            for (int q = 0; q < 4; q++) acc[mi][ni][q] = 0.f;

    const int arow = tid >> 2, aq = (tid & 3) * 4;
    const int bt = tid >> 4, bcs = (tid & 15) * 16;
    const int lr = lane >> 2, lk = (lane & 3) * 2;

    const __nv_bfloat16* php = g_Ph + ((size_t)b * 64 + arow) * T_MAX + aq;
    const __nv_bfloat16* plp = g_Pl + ((size_t)b * 64 + arow) * T_MAX + aq;

    for (int kc = 0; kc < 64; kc++) {
        const int tk0 = split * 1024 + kc * 16;
        __syncthreads();
        *(uint64_t*)&Ah[arow * SROWP + aq] = *(const uint64_t*)(php + tk0);
        *(uint64_t*)&Al[arow * SROWP + aq] = *(const uint64_t*)(plp + tk0);
        {
            const int tg = tk0 + bt;
            const float* src = (tg >= T_START)
                ? g_kvnew + (size_t)(b * N_S + tg - T_START) * KVPE + c0 + bcs
                : kvc + ((size_t)b * T_MAX + tg) * D_KVL + c0 + bcs;
#pragma unroll
            for (int j = 0; j < 16; j += 4) {
                float4 v = *(const float4*)(src + j);
                __nv_bfloat16 h; float f;
                f = v.x; h = __float2bfloat16(f);
                Bh[(bcs + j + 0) * SROWP + bt] = h;
                Bl[(bcs + j + 0) * SROWP + bt] = __float2bfloat16(f - __bfloat162float(h));
                f = v.y; h = __float2bfloat16(f);
                Bh[(bcs + j + 1) * SROWP + bt] = h;
                Bl[(bcs + j + 1) * SROWP + bt] = __float2bfloat16(f - __bfloat162float(h));
                f = v.z; h = __float2bfloat16(f);
                Bh[(bcs + j + 2) * SROWP + bt] = h;
                Bl[(bcs + j + 2) * SROWP + bt] = __float2bfloat16(f - __bfloat162float(h));
                f = v.w; h = __float2bfloat16(f);
                Bh[(bcs + j + 3) * SROWP + bt] = h;
                Bl[(bcs + j + 3) * SROWP + bt] = __float2bfloat16(f - __bfloat162float(h));
            }
        }
        __syncthreads();

        uint32_t ah[2][4], al[2][4];
#pragma unroll
        for (int mi = 0; mi < 2; mi++) {
            const int R = wm * 32 + mi * 16 + lr;
            ah[mi][0] = *(uint32_t*)&Ah[R * SROWP + lk];
            ah[mi][1] = *(uint32_t*)&Ah[(R + 8) * SROWP + lk];
            ah[mi][2] = *(uint32_t*)&Ah[R * SROWP + lk + 8];
            ah[mi][3] = *(uint32_t*)&Ah[(R + 8) * SROWP + lk + 8];
            al[mi][0] = *(uint32_t*)&Al[R * SROWP + lk];
            al[mi][1] = *(uint32_t*)&Al[(R + 8) * SROWP + lk];
            al[mi][2] = *(uint32_t*)&Al[R * SROWP + lk + 8];
            al[mi][3] = *(uint32_t*)&Al[(R + 8) * SROWP + lk + 8];
        }
#pragma unroll
        for (int ni = 0; ni < 8; ni++) {
            const int C = wc * 64 + ni * 8 + lr;
            uint32_t bh0 = *(uint32_t*)&Bh[C * SROWP + lk];
            uint32_t bh1 = *(uint32_t*)&Bh[C * SROWP + lk + 8];
            uint32_t bl0 = *(uint32_t*)&Bl[C * SROWP + lk];
            uint32_t bl1 = *(uint32_t*)&Bl[C * SROWP + lk + 8];
#pragma unroll
            for (int mi = 0; mi < 2; mi++) {
                mma_bf16(acc[mi][ni], ah[mi], bh0, bh1);
                mma_bf16(acc[mi][ni], ah[mi], bl0, bl1);
                mma_bf16(acc[mi][ni], al[mi], bh0, bh1);
            }
        }
    }

#pragma unroll
    for (int mi = 0; mi < 2; mi++) {
#pragma unroll
        for (int ni = 0; ni < 8; ni++) {
            const int r = wm * 32 + mi * 16 + lr;
            const int c = c0 + wc * 64 + ni * 8 + lk;
            float* p = g_part + (((size_t)(b * 8 + split) * 64 + r) * D_KVL + c);
            *(float2*)p = make_float2(acc[mi][ni][0], acc[mi][ni][1]);
            *(float2*)(p + (size_t)8 * D_KVL) = make_float2(acc[mi][ni][2], acc[mi][ni][3]);
        }
    }
}

// =======================================================================
// Reduce attn partials over 8 splits and normalize by l.
// =======================================================================
__global__ void k_attnred()
{
    const int i = blockIdx.x * 256 + threadIdx.x;
    if (i >= N_B * 64 * D_KVL) return;
    const int c = i & 511;
    const int r = (i >> 9) & 63;
    const int b = i >> 15;
    float s = 0.f;
#pragma unroll
    for (int k = 0; k < 8; k++)
        s += g_part[((size_t)(b * 8 + k) * 64 + r) * D_KVL + c];
    g_attn[((size_t)b * 64 + r) * D_KVL + c] = s / g_l[b * 64 + r];
}

// =======================================================================
// V projection, split-K over c (512 -> 4 x 128). grid (4 kz, 2 mtile, 16 h).
// =======================================================================
__global__ void k_projv(const float* __restrict__ wkvb)
{
    __shared__ float As[BK][BM];
    __shared__ float Bs[BK][BN];
    const int h = blockIdx.z, tid = threadIdx.x;
    const int kz = blockIdx.x;
    const int tx = tid & 15, ty = tid >> 4;
    const int m0 = blockIdx.y * BM;
    const int am = tid >> 2, ak = (tid & 3) << 2;
    const int bt = tid >> 1, bkq = (tid & 1) << 3;

    const int lm = m0 + am;
    const int arowi = (lm >> 2) * 64 + h * 4 + (lm & 3);
    const float* arp = g_attn + (size_t)arowi * D_KVL;
    const float* brp = wkvb + (size_t)(h * 256 + 128 + bt) * D_KVL;

    float acc[4][8];
#pragma unroll
    for (int i = 0; i < 4; i++)
#pragma unroll
        for (int j = 0; j < 8; j++) acc[i][j] = 0.f;

    const int kbeg = kz * 128, kend = kbeg + 128;
    for (int k0 = kbeg; k0 < kend; k0 += BK) {
        float4 av = *(const float4*)(arp + k0 + ak);
        As[ak + 0][am] = av.x; As[ak + 1][am] = av.y;
        As[ak + 2][am] = av.z; As[ak + 3][am] = av.w;
        float4 b0 = *(const float4*)(brp + k0 + bkq);
        float4 b1 = *(const float4*)(brp + k0 + bkq + 4);
        Bs[bkq + 0][bt] = b0.x; Bs[bkq + 1][bt] = b0.y;
        Bs[bkq + 2][bt] = b0.z; Bs[bkq + 3][bt] = b0.w;
        Bs[bkq + 4][bt] = b1.x; Bs[bkq + 5][bt] = b1.y;
        Bs[bkq + 6][bt] = b1.z; Bs[bkq + 7][bt] = b1.w;
        __syncthreads();
#pragma unroll
        for (int kk = 0; kk < BK; kk++) {
            float a[4], bb[8];
            *(float4*)a      = *(const float4*)&As[kk][ty << 2];
            *(float4*)&bb[0] = *(const float4*)&Bs[kk][tx << 3];
            *(float4*)&bb[4] = *(const float4*)&Bs[kk][(tx << 3) + 4];
#pragma unroll
            for (int i = 0; i < 4; i++)
#pragma unroll
                for (int j = 0; j < 8; j++)
                    acc[i][j] = fmaf(a[i], bb[j], acc[i][j]);
        }
        __syncthreads();
    }
#pragma unroll
    for (int i = 0; i < 4; i++) {
        const int m = m0 + (ty << 2) + i;
        float* cp = g_red + (size_t)kz * N_TOK * 2048 + (size_t)m * 2048 + h * D_V + (tx << 3);
#pragma unroll
        for (int j = 0; j < 8; j++) cp[j] = acc[i][j];
    }
}

// =======================================================================
// launch
// =======================================================================
extern "C" void kernel_launch(void* const* d_in, const int* in_sizes, int n_in,
                              void* d_out, int out_size)
{
    (void)in_sizes; (void)n_in; (void)out_size;
    const float* x     = (const float*)d_in[0];
    const float* wq_a  = (const float*)d_in[1];
    const float* qnw   = (const float*)d_in[2];
    const float* wq_b  = (const float*)d_in[3];
    const float* wkv_a = (const float*)d_in[4];
    const float* kvnw  = (const float*)d_in[5];
    const float* wkv_b = (const float*)d_in[6];
    const float* wo    = (const float*)d_in[7];
    const float* kvc   = (const float*)d_in[8];
    const float* pec   = (const float*)d_in[9];
    const float* fc    = (const float*)d_in[10];
    const float* fs    = (const float*)d_in[11];
    float* out = (float*)d_out;

    k_sgemm_xqa<<<dim3(D_QL / BN, 2, 8), 256>>>(x, wq_a);
    k_red_t1<<<(N_TOK * D_QL + 255) / 256, 256>>>();
    k_rms_q<<<N_TOK, 256>>>(qnw);
    k_sgemm_qb<<<dim3(D_QB / BN, 2, 4), 256>>>(wq_b);
    k_red_q<<<(N_TOK * D_QB + 255) / 256, 256>>>();
    k_sgemm_kva<<<dim3((KVPE + BN - 1) / BN, 2, 16), 256>>>(x, wkv_a);
    k_red_kvf<<<(N_TOK * KVPE + 255) / 256, 256>>>();
    k_kvprep<<<N_TOK, 128>>>(kvnw, fc, fs);
    k_absorb<<<dim3(D_KVL / BN, 2, N_H), 256>>>(wkv_b);
    k_qrope<<<256, 256>>>(fc, fs);
    k_qsplit<<<(N_B * 64 * KVPE + 255) / 256, 256>>>();
    k_scores_mma<<<dim3(T_MAX / 256, N_B), 256>>>(kvc, pec);
    k_rowsum<<<dim3(64, N_B), 256>>>();
    k_attnout_mma<<<dim3(2, 8, N_B), 256>>>(kvc);
    k_attnred<<<(N_B * 64 * D_KVL + 255) / 256, 256>>>();
    k_projv<<<dim3(4, 2, N_H), 256>>>(wkv_b);
    k_red_o<<<(N_TOK * 2048 + 255) / 256, 256>>>();
    k_sgemm_wo<<<dim3(2048 / BN, 2, 8), 256>>>(wo);
    k_red_out<<<(N_TOK * 2048 + 255) / 256, 256>>>(out);
}

// round 4
// speedup vs baseline: 3.0481x; 1.6655x over previous
#include <cuda_runtime.h>
#include <cuda_bf16.h>
#include <math.h>
#include <stdint.h>

// ---------------- problem constants ----------------
#define N_TOK   128
#define N_B     32
#define N_S     4
#define N_H     16
#define D_MODEL 2048
#define D_QL    1536
#define D_QB    3072
#define D_KVL   512
#define D_NOPE  128
#define D_ROPE  64
#define D_V     128
#define D_HD    192
#define T_MAX   8192
#define T_START 8188
#define KVPE    576
#define ATT_SCALE 0.07216878364870323f

#define BM 64
#define BN 128
#define BK 16
#define SR 24            // smem row stride (bf16) for 16-wide k tiles (conflict-free ldmatrix)
#define BR 264           // smem row stride (bf16) for 256-wide c tiles in attnout
#define NSPLIT 8         // attnout splits over tokens

// ---------------- static scratch ----------------
__device__ float g_t1[N_TOK * D_QL];
__device__ float g_q[N_TOK * D_QB];
__device__ float g_kvf[N_TOK * KVPE];
__device__ float g_kvnew[N_TOK * KVPE];
__device__ float g_qabs[N_B * 64 * KVPE];
__device__ __nv_bfloat16 g_qh[N_B * 64 * KVPE];
__device__ __nv_bfloat16 g_ql[N_B * 64 * KVPE];
__device__ __nv_bfloat16 g_Kh[(size_t)N_B * T_MAX * KVPE];   // pre-split cache hi
__device__ __nv_bfloat16 g_Kl[(size_t)N_B * T_MAX * KVPE];   // pre-split cache lo
__device__ __nv_bfloat16 g_Ph[(size_t)N_B * 64 * T_MAX];
__device__ __nv_bfloat16 g_Pl[(size_t)N_B * 64 * T_MAX];
__device__ float g_lp[N_B * 64 * 4 * 64];                    // rowsum partials [b][tt64][wt4][r64]
__device__ float g_l[N_B * 64];
__device__ float g_part[(size_t)N_B * NSPLIT * 64 * D_KVL];
__device__ float g_attn[N_B * 64 * D_KVL];
__device__ float g_o[N_TOK * 2048];
__device__ float g_red[2200000];

// ---------------- helpers ----------------
__device__ __forceinline__ uint32_t packbf2(__nv_bfloat16 a, __nv_bfloat16 b) {
    __nv_bfloat162 t = __halves2bfloat162(a, b);
    return *reinterpret_cast<uint32_t*>(&t);
}
__device__ __forceinline__ void split2(float a, float b, uint32_t& h, uint32_t& l) {
    __nv_bfloat16 ah = __float2bfloat16(a);
    __nv_bfloat16 bh = __float2bfloat16(b);
    __nv_bfloat16 al = __float2bfloat16(a - __bfloat162float(ah));
    __nv_bfloat16 bl = __float2bfloat16(b - __bfloat162float(bh));
    h = packbf2(ah, bh);
    l = packbf2(al, bl);
}
__device__ __forceinline__ void mma_bf16(float* c, const uint32_t* a, uint32_t b0, uint32_t b1) {
    asm volatile(
        "mma.sync.aligned.m16n8k16.row.col.f32.bf16.bf16.f32 "
        "{%0,%1,%2,%3}, {%4,%5,%6,%7}, {%8,%9}, {%0,%1,%2,%3};\n"
        : "+f"(c[0]), "+f"(c[1]), "+f"(c[2]), "+f"(c[3])
        : "r"(a[0]), "r"(a[1]), "r"(a[2]), "r"(a[3]), "r"(b0), "r"(b1));
}
__device__ __forceinline__ void cpa16(void* s, const void* g) {
    uint32_t sa = (uint32_t)__cvta_generic_to_shared(s);
    asm volatile("cp.async.cg.shared.global [%0], [%1], 16;\n" :: "r"(sa), "l"(g));
}
#define CP_COMMIT() asm volatile("cp.async.commit_group;\n")
#define CP_WAIT1()  asm volatile("cp.async.wait_group 1;\n")
#define CP_WAIT0()  asm volatile("cp.async.wait_group 0;\n")

__device__ __forceinline__ void ldsm4(uint32_t& r0, uint32_t& r1, uint32_t& r2, uint32_t& r3,
                                      const void* p) {
    uint32_t a = (uint32_t)__cvta_generic_to_shared(p);
    asm volatile("ldmatrix.sync.aligned.m8n8.x4.shared.b16 {%0,%1,%2,%3}, [%4];\n"
                 : "=r"(r0), "=r"(r1), "=r"(r2), "=r"(r3) : "r"(a));
}
__device__ __forceinline__ void ldsm4t(uint32_t& r0, uint32_t& r1, uint32_t& r2, uint32_t& r3,
                                       const void* p) {
    uint32_t a = (uint32_t)__cvta_generic_to_shared(p);
    asm volatile("ldmatrix.sync.aligned.m8n8.x4.trans.shared.b16 {%0,%1,%2,%3}, [%4];\n"
                 : "=r"(r0), "=r"(r1), "=r"(r2), "=r"(r3) : "r"(a));
}

// =======================================================================
// fp32 SGEMM NN body with K-range (for split-K). Tile 64x128, 256 thr.
// =======================================================================
__device__ __forceinline__ void sgemm_nn_body(
    const float* __restrict__ A, int lda,
    const float* __restrict__ B, int ldb,
    float* __restrict__ C, int ldc,
    int N, int kbeg, int kend)
{
    __shared__ float As[BK][BM];
    __shared__ float Bs[BK][BN];
    const int tid = threadIdx.x;
    const int tx = tid & 15, ty = tid >> 4;
    const int m0 = blockIdx.y * BM;
    const int n0 = blockIdx.x * BN;
    const int am = tid >> 2, ak = (tid & 3) << 2;
    const int bkr = tid >> 4, bn = (tid & 15) << 3;

    float acc[4][8];
#pragma unroll
    for (int i = 0; i < 4; i++)
#pragma unroll
        for (int j = 0; j < 8; j++) acc[i][j] = 0.f;

    for (int k0 = kbeg; k0 < kend; k0 += BK) {
        float4 av = *(const float4*)(A + (size_t)(m0 + am) * lda + k0 + ak);
        As[ak + 0][am] = av.x; As[ak + 1][am] = av.y;
        As[ak + 2][am] = av.z; As[ak + 3][am] = av.w;
        const float* bp = B + (size_t)(k0 + bkr) * ldb + n0 + bn;
        if (n0 + bn + 7 < N) {
            *(float4*)&Bs[bkr][bn]     = *(const float4*)bp;
            *(float4*)&Bs[bkr][bn + 4] = *(const float4*)(bp + 4);
        } else {
#pragma unroll
            for (int j = 0; j < 8; j++)
                Bs[bkr][bn + j] = (n0 + bn + j < N) ? bp[j] : 0.f;
        }
        __syncthreads();
#pragma unroll
        for (int kk = 0; kk < BK; kk++) {
            float a[4], bb[8];
            *(float4*)a      = *(const float4*)&As[kk][ty << 2];
            *(float4*)&bb[0] = *(const float4*)&Bs[kk][tx << 3];
            *(float4*)&bb[4] = *(const float4*)&Bs[kk][(tx << 3) + 4];
#pragma unroll
            for (int i = 0; i < 4; i++)
#pragma unroll
                for (int j = 0; j < 8; j++)
                    acc[i][j] = fmaf(a[i], bb[j], acc[i][j]);
        }
        __syncthreads();
    }
#pragma unroll
    for (int i = 0; i < 4; i++) {
        int m = m0 + (ty << 2) + i;
        float* cp = C + (size_t)m * ldc + n0 + (tx << 3);
#pragma unroll
        for (int j = 0; j < 8; j++)
            if (n0 + (tx << 3) + j < N) cp[j] = acc[i][j];
    }
}

// ---------------- split-K GEMM wrappers ----------------
__global__ void k_sgemm_xqa(const float* __restrict__ x, const float* __restrict__ w) {
    const int z = blockIdx.z, ks = D_MODEL / 8;
    sgemm_nn_body(x, D_MODEL, w, D_QL, g_red + (size_t)z * N_TOK * D_QL, D_QL,
                  D_QL, z * ks, (z + 1) * ks);
}
__global__ void k_sgemm_qb(const float* __restrict__ w) {
    const int z = blockIdx.z, ks = D_QL / 4;
    sgemm_nn_body(g_t1, D_QL, w, D_QB, g_red + (size_t)z * N_TOK * D_QB, D_QB,
                  D_QB, z * ks, (z + 1) * ks);
}
__global__ void k_sgemm_kva(const float* __restrict__ x, const float* __restrict__ w) {
    const int z = blockIdx.z, ks = D_MODEL / 16;
    sgemm_nn_body(x, D_MODEL, w, KVPE, g_red + (size_t)z * N_TOK * KVPE, KVPE,
                  KVPE, z * ks, (z + 1) * ks);
}
__global__ void k_sgemm_wo(const float* __restrict__ w) {
    const int z = blockIdx.z, ks = 2048 / 8;
    sgemm_nn_body(g_o, 2048, w, 2048, g_red + (size_t)z * N_TOK * 2048, 2048,
                  2048, z * ks, (z + 1) * ks);
}

// ---------------- reduce wrappers ----------------
__device__ __forceinline__ void reduce_body(const float* __restrict__ src,
                                            float* __restrict__ dst, int mn, int splits) {
    int i = blockIdx.x * 256 + threadIdx.x;
    if (i >= mn) return;
    float s = 0.f;
    for (int k = 0; k < splits; k++) s += src[i + (size_t)k * mn];
    dst[i] = s;
}
__global__ void k_red_t1()  { reduce_body(g_red, g_t1,  N_TOK * D_QL, 8); }
__global__ void k_red_q()   { reduce_body(g_red, g_q,   N_TOK * D_QB, 4); }
__global__ void k_red_kvf() { reduce_body(g_red, g_kvf, N_TOK * KVPE, 16); }
__global__ void k_red_o()   { reduce_body(g_red, g_o,   N_TOK * 2048, 4); }
__global__ void k_red_out(float* __restrict__ out) { reduce_body(g_red, out, N_TOK * 2048, 8); }

// =======================================================================
// RMSNorm q_lora rows (1536)
// =======================================================================
__global__ void k_rms_q(const float* __restrict__ w)
{
    const int m = blockIdx.x, tid = threadIdx.x;
    float* row = g_t1 + (size_t)m * D_QL;
    float s = 0.f;
    for (int i = tid; i < D_QL / 4; i += 256) {
        float4 v = ((const float4*)row)[i];
        s += v.x * v.x + v.y * v.y + v.z * v.z + v.w * v.w;
    }
    __shared__ float sd[256];
    sd[tid] = s; __syncthreads();
    for (int o = 128; o > 0; o >>= 1) {
        if (tid < o) sd[tid] += sd[tid + o];
        __syncthreads();
    }
    const float inv = rsqrtf(sd[0] / (float)D_QL + 1e-6f);
    for (int i = tid; i < D_QL / 4; i += 256) {
        float4 v = ((const float4*)row)[i];
        float4 wv = ((const float4*)w)[i];
        v.x *= inv * wv.x; v.y *= inv * wv.y;
        v.z *= inv * wv.z; v.w *= inv * wv.w;
        ((float4*)row)[i] = v;
    }
}

// =======================================================================
// KV prep for the 4 new tokens per batch
// =======================================================================
__global__ void k_kvprep(const float* __restrict__ kvw,
                         const float* __restrict__ fc,
                         const float* __restrict__ fs)
{
    const int m = blockIdx.x, tid = threadIdx.x;
    const float* row = g_kvf + (size_t)m * KVPE;
    float* out = g_kvnew + (size_t)m * KVPE;
    float4 v = ((const float4*)row)[tid];
    float s = v.x * v.x + v.y * v.y + v.z * v.z + v.w * v.w;
    __shared__ float sd[128];
    sd[tid] = s; __syncthreads();
    for (int o = 64; o > 0; o >>= 1) {
        if (tid < o) sd[tid] += sd[tid + o];
        __syncthreads();
    }
    const float inv = rsqrtf(sd[0] / (float)D_KVL + 1e-6f);
    out[tid * 4 + 0] = v.x * inv * kvw[tid * 4 + 0];
    out[tid * 4 + 1] = v.y * inv * kvw[tid * 4 + 1];
    out[tid * 4 + 2] = v.z * inv * kvw[tid * 4 + 2];
    out[tid * 4 + 3] = v.w * inv * kvw[tid * 4 + 3];
    if (tid < 32) {
        const int sidx = m & 3;
        const float c = fc[sidx * 32 + tid], sn = fs[sidx * 32 + tid];
        const float x0 = row[512 + 2 * tid], x1 = row[512 + 2 * tid + 1];
        out[512 + 2 * tid]     = x0 * c - x1 * sn;
        out[512 + 2 * tid + 1] = x0 * sn + x1 * c;
    }
}

// =======================================================================
// Pre-convert the full cache (kvc + pec, with the last 4 tokens replaced by
// g_kvnew) into bf16 hi/lo rows [b][t][576]. Memory-bound.
// =======================================================================
__global__ void k_cvt(const float* __restrict__ kvc, const float* __restrict__ pec)
{
    const uint32_t g = blockIdx.x * 256 + threadIdx.x;   // one 8-elem group
    if (g >= (uint32_t)N_B * T_MAX * (KVPE / 8)) return;
    const uint32_t row = g / (KVPE / 8);
    const int seg = (g - row * (KVPE / 8)) * 8;
    const int t = row & (T_MAX - 1);
    const int b = row >> 13;

    const float* src;
    if (t >= T_START)       src = g_kvnew + (size_t)((b << 2) + (t - T_START)) * KVPE + seg;
    else if (seg < D_KVL)   src = kvc + (size_t)row * D_KVL + seg;
    else                    src = pec + (size_t)row * D_ROPE + (seg - D_KVL);

    float4 v0 = *(const float4*)src;
    float4 v1 = *(const float4*)(src + 4);
    uint32_t h[4], l[4];
    split2(v0.x, v0.y, h[0], l[0]);
    split2(v0.z, v0.w, h[1], l[1]);
    split2(v1.x, v1.y, h[2], l[2]);
    split2(v1.z, v1.w, h[3], l[3]);
    *(uint4*)(g_Kh + (size_t)row * KVPE + seg) = *(uint4*)h;
    *(uint4*)(g_Kl + (size_t)row * KVPE + seg) = *(uint4*)l;
}

// =======================================================================
// Absorb q_nope through wkv_b[:, :128, :] -> g_qabs[:, :512]
// =======================================================================
__global__ void k_absorb(const float* __restrict__ wkvb)
{
    __shared__ float As[BK][BM];
    __shared__ float Bs[BK][BN];
    const int h = blockIdx.z, tid = threadIdx.x;
    const int tx = tid & 15, ty = tid >> 4;
    const int m0 = blockIdx.y * BM, n0 = blockIdx.x * BN;
    const int am = tid >> 2, ak = (tid & 3) << 2;
    const int bkr = tid >> 4, bn = (tid & 15) << 3;
    const float* A = g_q + h * D_HD;
    const float* B = wkvb + (size_t)(h * 256) * D_KVL;
    float acc[4][8];
#pragma unroll
    for (int i = 0; i < 4; i++)
#pragma unroll
        for (int j = 0; j < 8; j++) acc[i][j] = 0.f;
    for (int k0 = 0; k0 < D_NOPE; k0 += BK) {
        float4 av = *(const float4*)(A + (size_t)(m0 + am) * D_QB + k0 + ak);
        As[ak + 0][am] = av.x; As[ak + 1][am] = av.y;
        As[ak + 2][am] = av.z; As[ak + 3][am] = av.w;
        const float* bp = B + (size_t)(k0 + bkr) * D_KVL + n0 + bn;
        *(float4*)&Bs[bkr][bn]     = *(const float4*)bp;
        *(float4*)&Bs[bkr][bn + 4] = *(const float4*)(bp + 4);
        __syncthreads();
#pragma unroll
        for (int kk = 0; kk < BK; kk++) {
            float a[4], bb[8];
            *(float4*)a      = *(const float4*)&As[kk][ty << 2];
            *(float4*)&bb[0] = *(const float4*)&Bs[kk][tx << 3];
            *(float4*)&bb[4] = *(const float4*)&Bs[kk][(tx << 3) + 4];
#pragma unroll
            for (int i = 0; i < 4; i++)
#pragma unroll
                for (int j = 0; j < 8; j++)
                    acc[i][j] = fmaf(a[i], bb[j], acc[i][j]);
        }
        __syncthreads();
    }
#pragma unroll
    for (int i = 0; i < 4; i++) {
        const int m = m0 + (ty << 2) + i;
        const int row = (m >> 2) * 64 + h * 4 + (m & 3);
        float* cp = g_qabs + (size_t)row * KVPE + n0 + (tx << 3);
#pragma unroll
        for (int j = 0; j < 8; j++) cp[j] = acc[i][j];
    }
}

// =======================================================================
// Rope q_pe -> g_qabs[..., 512:576]
// =======================================================================
__global__ void k_qrope(const float* __restrict__ fc, const float* __restrict__ fs)
{
    const int idx = blockIdx.x * blockDim.x + threadIdx.x;
    const int j = idx & 31, h = (idx >> 5) & 15, m = idx >> 9, s = m & 3;
    const float c = fc[s * 32 + j], sn = fs[s * 32 + j];
    const float* src = g_q + (size_t)m * D_QB + h * D_HD + D_NOPE + 2 * j;
    const float x0 = src[0], x1 = src[1];
    const int row = (m >> 2) * 64 + h * 4 + s;
    float* dst = g_qabs + (size_t)row * KVPE + 512 + 2 * j;
    dst[0] = x0 * c - x1 * sn;
    dst[1] = x0 * sn + x1 * c;
}

// =======================================================================
// Split g_qabs fp32 -> bf16 hi/lo
// =======================================================================
__global__ void k_qsplit()
{
    const int i = blockIdx.x * 256 + threadIdx.x;
    if (i >= N_B * 64 * KVPE) return;
    float v = g_qabs[i];
    __nv_bfloat16 h = __float2bfloat16(v);
    g_qh[i] = h;
    g_ql[i] = __float2bfloat16(v - __bfloat162float(h));
}

// =======================================================================
// Scores v2: P = exp(scale * Q' KV^T), bf16 hi/lo inputs pre-split,
// cp.async double-buffered, ldmatrix fragments, fused rowsum partials.
// Block: 64 q-rows x 128 tokens. 8 warps = 2(m) x 4(t). grid (64 tt, 32 b).
// =======================================================================
__global__ __launch_bounds__(256, 2) void k_scores2()
{
    __shared__ __nv_bfloat16 Qh[2][64 * SR], Ql[2][64 * SR];
    __shared__ __nv_bfloat16 Kh[2][128 * SR], Kl[2][128 * SR];

    const int tid = threadIdx.x;
    const int lane = tid & 31, w = tid >> 5;
    const int wm = w & 1, wt = w >> 1;
    const int b = blockIdx.y;
    const int tt = blockIdx.x;
    const int t0 = tt * 128;

    float acc[2][4][4];
#pragma unroll
    for (int mi = 0; mi < 2; mi++)
#pragma unroll
        for (int ni = 0; ni < 4; ni++)
#pragma unroll
            for (int q = 0; q < 4; q++) acc[mi][ni][q] = 0.f;

    // staging roles
    const int srow = tid >> 1, shf = (tid & 1) * 8;      // 128 rows x 2 halves
    const __nv_bfloat16* gqh = g_qh + ((size_t)b * 64 + (srow & 63)) * KVPE + shf;
    const __nv_bfloat16* gql = g_ql + ((size_t)b * 64 + (srow & 63)) * KVPE + shf;
    const __nv_bfloat16* gkh = g_Kh + ((size_t)b * T_MAX + t0 + srow) * KVPE + shf;
    const __nv_bfloat16* gkl = g_Kl + ((size_t)b * T_MAX + t0 + srow) * KVPE + shf;

#define SC_STAGE(c, buf) do {                                             \
        const int k0_ = (c) * 16;                                         \
        if (tid < 128) {                                                  \
            cpa16(&Qh[buf][srow * SR + shf], gqh + k0_);                  \
            cpa16(&Ql[buf][srow * SR + shf], gql + k0_);                  \
        }                                                                 \
        cpa16(&Kh[buf][srow * SR + shf], gkh + k0_);                      \
        cpa16(&Kl[buf][srow * SR + shf], gkl + k0_);                      \
        CP_COMMIT();                                                      \
    } while (0)

    const int lg = lane >> 3, lidx = lane & 7;
    const int lr = lane >> 2, lk = (lane & 3) * 2;

    SC_STAGE(0, 0);

    for (int c = 0; c < KVPE / 16; c++) {
        const int buf = c & 1;
        if (c + 1 < KVPE / 16) SC_STAGE(c + 1, (c + 1) & 1);
        if (c + 1 < KVPE / 16) { CP_WAIT1(); } else { CP_WAIT0(); }
        __syncthreads();

        uint32_t ah[2][4], al[2][4];
#pragma unroll
        for (int mi = 0; mi < 2; mi++) {
            const int arow = wm * 32 + mi * 16 + ((lg & 1) << 3) + lidx;
            const int acol = (lg >> 1) << 3;
            ldsm4(ah[mi][0], ah[mi][1], ah[mi][2], ah[mi][3], &Qh[buf][arow * SR + acol]);
            ldsm4(al[mi][0], al[mi][1], al[mi][2], al[mi][3], &Ql[buf][arow * SR + acol]);
        }
#pragma unroll
        for (int p = 0; p < 2; p++) {
            const int T = wt * 32 + p * 16;
            const int brow = T + ((lg >> 1) << 3) + lidx;
            const int bcol = (lg & 1) << 3;
            uint32_t bh[4], bl[4];
            ldsm4(bh[0], bh[1], bh[2], bh[3], &Kh[buf][brow * SR + bcol]);
            ldsm4(bl[0], bl[1], bl[2], bl[3], &Kl[buf][brow * SR + bcol]);
#pragma unroll
            for (int mi = 0; mi < 2; mi++) {
                mma_bf16(acc[mi][2 * p],     ah[mi], bh[0], bh[1]);
                mma_bf16(acc[mi][2 * p],     ah[mi], bl[0], bl[1]);
                mma_bf16(acc[mi][2 * p],     al[mi], bh[0], bh[1]);
                mma_bf16(acc[mi][2 * p + 1], ah[mi], bh[2], bh[3]);
                mma_bf16(acc[mi][2 * p + 1], ah[mi], bl[2], bl[3]);
                mma_bf16(acc[mi][2 * p + 1], al[mi], bh[2], bh[3]);
            }
        }
        __syncthreads();
    }
#undef SC_STAGE

    // epilogue: exp, P hi/lo store, fused rowsum partials
    float s0[2] = {0.f, 0.f}, s1[2] = {0.f, 0.f};
#pragma unroll
    for (int mi = 0; mi < 2; mi++) {
#pragma unroll
        for (int ni = 0; ni < 4; ni++) {
            const int r = wm * 32 + mi * 16 + lr;
            const int t = t0 + wt * 32 + ni * 8 + lk;
            size_t base = ((size_t)b * 64 + r) * T_MAX + t;
            float e0 = __expf(acc[mi][ni][0] * ATT_SCALE);
            float e1 = __expf(acc[mi][ni][1] * ATT_SCALE);
            float e2 = __expf(acc[mi][ni][2] * ATT_SCALE);
            float e3 = __expf(acc[mi][ni][3] * ATT_SCALE);
            s0[mi] += e0 + e1;
            s1[mi] += e2 + e3;
            uint32_t h, l;
            split2(e0, e1, h, l);
            *(uint32_t*)&g_Ph[base] = h;
            *(uint32_t*)&g_Pl[base] = l;
            split2(e2, e3, h, l);
            *(uint32_t*)&g_Ph[base + (size_t)8 * T_MAX] = h;
            *(uint32_t*)&g_Pl[base + (size_t)8 * T_MAX] = l;
        }
    }
#pragma unroll
    for (int mi = 0; mi < 2; mi++) {
        s0[mi] += __shfl_xor_sync(0xffffffffu, s0[mi], 1);
        s0[mi] += __shfl_xor_sync(0xffffffffu, s0[mi], 2);
        s1[mi] += __shfl_xor_sync(0xffffffffu, s1[mi], 1);
        s1[mi] += __shfl_xor_sync(0xffffffffu, s1[mi], 2);
        if ((lane & 3) == 0) {
            const int r = wm * 32 + mi * 16 + lr;
            float* dst = g_lp + ((size_t)(b * 64 + tt) * 4 + wt) * 64;
            dst[r]     = s0[mi];
            dst[r + 8] = s1[mi];
        }
    }
}

// =======================================================================
// Reduce rowsum partials -> g_l
// =======================================================================
__global__ void k_lred()
{
    const int b = blockIdx.x, r = threadIdx.x;
    float s = 0.f;
    for (int i = 0; i < 256; i++)
        s += g_lp[((size_t)(b * 64 + (i >> 2)) * 4 + (i & 3)) * 64 + r];
    g_l[b * 64 + r] = s;
}

// =======================================================================
// Attention out v2: partial = P @ KV over 1024-token slice.
// cp.async double-buffered; B fragments via ldmatrix.trans (HW transpose).
// Block 64 rows x 256 cols; 8 warps = 2(m) x 4(c). grid (2, NSPLIT, 32).
// =======================================================================
__global__ __launch_bounds__(256, 2) void k_attnout2()
{
    __shared__ __nv_bfloat16 Ah[2][64 * SR], Al[2][64 * SR];
    __shared__ __nv_bfloat16 Bh[2][16 * BR], Bl[2][16 * BR];

    const int tid = threadIdx.x;
    const int lane = tid & 31, w = tid >> 5;
    const int wm = w & 1, wc = w >> 1;
    const int c0 = blockIdx.x * 256;
    const int split = blockIdx.y;
    const int b = blockIdx.z;

    float acc[2][8][4];
#pragma unroll
    for (int mi = 0; mi < 2; mi++)
#pragma unroll
        for (int ni = 0; ni < 8; ni++)
#pragma unroll
            for (int q = 0; q < 4; q++) acc[mi][ni][q] = 0.f;

    // staging roles
    const int arow = tid >> 1, ahf = (tid & 1) * 8;             // P rows (tid<128)
    const int bt = tid >> 4, bcs = (tid & 15) * 16;             // KV: t row, 16-col seg
    const int tbase = split * (T_MAX / NSPLIT);

    const __nv_bfloat16* gph = g_Ph + ((size_t)b * 64 + (arow & 63)) * T_MAX + tbase + ahf;
    const __nv_bfloat16* gpl = g_Pl + ((size_t)b * 64 + (arow & 63)) * T_MAX + tbase + ahf;
    const __nv_bfloat16* gbh = g_Kh + ((size_t)b * T_MAX + tbase + bt) * KVPE + c0 + bcs;
    const __nv_bfloat16* gbl = g_Kl + ((size_t)b * T_MAX + tbase + bt) * KVPE + c0 + bcs;

#define AO_STAGE(c, buf) do {                                              \
        const int tk_ = (c) * 16;                                          \
        if (tid < 128) {                                                   \
            cpa16(&Ah[buf][arow * SR + ahf], gph + tk_);                   \
            cpa16(&Al[buf][arow * SR + ahf], gpl + tk_);                   \
        }                                                                  \
        cpa16(&Bh[buf][bt * BR + bcs],     gbh + (size_t)tk_ * KVPE);      \
        cpa16(&Bh[buf][bt * BR + bcs + 8], gbh + (size_t)tk_ * KVPE + 8);  \
        cpa16(&Bl[buf][bt * BR + bcs],     gbl + (size_t)tk_ * KVPE);      \
        cpa16(&Bl[buf][bt * BR + bcs + 8], gbl + (size_t)tk_ * KVPE + 8);  \
        CP_COMMIT();                                                       \
    } while (0)

    const int lg = lane >> 3, lidx = lane & 7;
    const int lr = lane >> 2, lk = (lane & 3) * 2;
    const int NCH = (T_MAX / NSPLIT) / 16;

    AO_STAGE(0, 0);

    for (int c = 0; c < NCH; c++) {
        const int buf = c & 1;
        if (c + 1 < NCH) AO_STAGE(c + 1, (c + 1) & 1);
        if (c + 1 < NCH) { CP_WAIT1(); } else { CP_WAIT0(); }
        __syncthreads();

        uint32_t ah[2][4], al[2][4];
#pragma unroll
        for (int mi = 0; mi < 2; mi++) {
            const int r = wm * 32 + mi * 16 + ((lg & 1) << 3) + lidx;
            const int acol = (lg >> 1) << 3;
            ldsm4(ah[mi][0], ah[mi][1], ah[mi][2], ah[mi][3], &Ah[buf][r * SR + acol]);
            ldsm4(al[mi][0], al[mi][1], al[mi][2], al[mi][3], &Al[buf][r * SR + acol]);
        }
#pragma unroll
        for (int p = 0; p < 4; p++) {
            const int C = wc * 64 + p * 16;
            const int brow = ((lg & 1) << 3) + lidx;          // t row 0..15
            const int bcol = C + ((lg >> 1) << 3);
            uint32_t bh[4], bl[4];
            ldsm4t(bh[0], bh[1], bh[2], bh[3], &Bh[buf][brow * BR + bcol]);
            ldsm4t(bl[0], bl[1], bl[2], bl[3], &Bl[buf][brow * BR + bcol]);
#pragma unroll
            for (int mi = 0; mi < 2; mi++) {
                mma_bf16(acc[mi][2 * p],     ah[mi], bh[0], bh[1]);
                mma_bf16(acc[mi][2 * p],     ah[mi], bl[0], bl[1]);
                mma_bf16(acc[mi][2 * p],     al[mi], bh[0], bh[1]);
                mma_bf16(acc[mi][2 * p + 1], ah[mi], bh[2], bh[3]);
                mma_bf16(acc[mi][2 * p + 1], ah[mi], bl[2], bl[3]);
                mma_bf16(acc[mi][2 * p + 1], al[mi], bh[2], bh[3]);
            }
        }
        __syncthreads();
    }
#undef AO_STAGE

#pragma unroll
    for (int mi = 0; mi < 2; mi++) {
#pragma unroll
        for (int ni = 0; ni < 8; ni++) {
            const int r = wm * 32 + mi * 16 + lr;
            const int cc = c0 + wc * 64 + ni * 8 + lk;
            float* p = g_part + (((size_t)(b * NSPLIT + split) * 64 + r) * D_KVL + cc);
            *(float2*)p = make_float2(acc[mi][ni][0], acc[mi][ni][1]);
            *(float2*)(p + (size_t)8 * D_KVL) = make_float2(acc[mi][ni][2], acc[mi][ni][3]);
        }
    }
}

// =======================================================================
// Reduce attn partials over splits and normalize by l.
// =======================================================================
__global__ void k_attnred()
{
    const int i = blockIdx.x * 256 + threadIdx.x;
    if (i >= N_B * 64 * D_KVL) return;
    const int c = i & 511;
    const int r = (i >> 9) & 63;
    const int b = i >> 15;
    float s = 0.f;
#pragma unroll
    for (int k = 0; k < NSPLIT; k++)
        s += g_part[((size_t)(b * NSPLIT + k) * 64 + r) * D_KVL + c];
    g_attn[((size_t)b * 64 + r) * D_KVL + c] = s / g_l[b * 64 + r];
}

// =======================================================================
// V projection, split-K over c (512 -> 4 x 128). grid (4 kz, 2 mtile, 16 h).
// =======================================================================
__global__ void k_projv(const float* __restrict__ wkvb)
{
    __shared__ float As[BK][BM];
    __shared__ float Bs[BK][BN];
    const int h = blockIdx.z, tid = threadIdx.x;
    const int kz = blockIdx.x;
    const int tx = tid & 15, ty = tid >> 4;
    const int m0 = blockIdx.y * BM;
    const int am = tid >> 2, ak = (tid & 3) << 2;
    const int bt = tid >> 1, bkq = (tid & 1) << 3;

    const int lm = m0 + am;
    const int arowi = (lm >> 2) * 64 + h * 4 + (lm & 3);
    const float* arp = g_attn + (size_t)arowi * D_KVL;
    const float* brp = wkvb + (size_t)(h * 256 + 128 + bt) * D_KVL;

    float acc[4][8];
#pragma unroll
    for (int i = 0; i < 4; i++)
#pragma unroll
        for (int j = 0; j < 8; j++) acc[i][j] = 0.f;

    const int kbeg = kz * 128, kend = kbeg + 128;
    for (int k0 = kbeg; k0 < kend; k0 += BK) {
        float4 av = *(const float4*)(arp + k0 + ak);
        As[ak + 0][am] = av.x; As[ak + 1][am] = av.y;
        As[ak + 2][am] = av.z; As[ak + 3][am] = av.w;
        float4 b0 = *(const float4*)(brp + k0 + bkq);
        float4 b1 = *(const float4*)(brp + k0 + bkq + 4);
        Bs[bkq + 0][bt] = b0.x; Bs[bkq + 1][bt] = b0.y;
        Bs[bkq + 2][bt] = b0.z; Bs[bkq + 3][bt] = b0.w;
        Bs[bkq + 4][bt] = b1.x; Bs[bkq + 5][bt] = b1.y;
        Bs[bkq + 6][bt] = b1.z; Bs[bkq + 7][bt] = b1.w;
        __syncthreads();
#pragma unroll
        for (int kk = 0; kk < BK; kk++) {
            float a[4], bb[8];
            *(float4*)a      = *(const float4*)&As[kk][ty << 2];
            *(float4*)&bb[0] = *(const float4*)&Bs[kk][tx << 3];
            *(float4*)&bb[4] = *(const float4*)&Bs[kk][(tx << 3) + 4];
#pragma unroll
            for (int i = 0; i < 4; i++)
#pragma unroll
                for (int j = 0; j < 8; j++)
                    acc[i][j] = fmaf(a[i], bb[j], acc[i][j]);
        }
        __syncthreads();
    }
#pragma unroll
    for (int i = 0; i < 4; i++) {
        const int m = m0 + (ty << 2) + i;
        float* cp = g_red + (size_t)kz * N_TOK * 2048 + (size_t)m * 2048 + h * D_V + (tx << 3);
#pragma unroll
        for (int j = 0; j < 8; j++) cp[j] = acc[i][j];
    }
}

// =======================================================================
// launch
// =======================================================================
extern "C" void kernel_launch(void* const* d_in, const int* in_sizes, int n_in,
                              void* d_out, int out_size)
{
    (void)in_sizes; (void)n_in; (void)out_size;
    const float* x     = (const float*)d_in[0];
    const float* wq_a  = (const float*)d_in[1];
    const float* qnw   = (const float*)d_in[2];
    const float* wq_b  = (const float*)d_in[3];
    const float* wkv_a = (const float*)d_in[4];
    const float* kvnw  = (const float*)d_in[5];
    const float* wkv_b = (const float*)d_in[6];
    const float* wo    = (const float*)d_in[7];
    const float* kvc   = (const float*)d_in[8];
    const float* pec   = (const float*)d_in[9];
    const float* fc    = (const float*)d_in[10];
    const float* fs    = (const float*)d_in[11];
    float* out = (float*)d_out;

    k_sgemm_xqa<<<dim3(D_QL / BN, 2, 8), 256>>>(x, wq_a);
    k_red_t1<<<(N_TOK * D_QL + 255) / 256, 256>>>();
    k_rms_q<<<N_TOK, 256>>>(qnw);
    k_sgemm_qb<<<dim3(D_QB / BN, 2, 4), 256>>>(wq_b);
    k_red_q<<<(N_TOK * D_QB + 255) / 256, 256>>>();
    k_sgemm_kva<<<dim3((KVPE + BN - 1) / BN, 2, 16), 256>>>(x, wkv_a);
    k_red_kvf<<<(N_TOK * KVPE + 255) / 256, 256>>>();
    k_kvprep<<<N_TOK, 128>>>(kvnw, fc, fs);
    k_cvt<<<(N_B * T_MAX * (KVPE / 8) + 255) / 256, 256>>>(kvc, pec);
    k_absorb<<<dim3(D_KVL / BN, 2, N_H), 256>>>(wkv_b);
    k_qrope<<<256, 256>>>(fc, fs);
    k_qsplit<<<(N_B * 64 * KVPE + 255) / 256, 256>>>();
    k_scores2<<<dim3(T_MAX / 128, N_B), 256>>>();
    k_lred<<<N_B, 64>>>();
    k_attnout2<<<dim3(2, NSPLIT, N_B), 256>>>();
    k_attnred<<<(N_B * 64 * D_KVL + 255) / 256, 256>>>();
    k_projv<<<dim3(4, 2, N_H), 256>>>(wkv_b);
    k_red_o<<<(N_TOK * 2048 + 255) / 256, 256>>>();
    k_sgemm_wo<<<dim3(2048 / BN, 2, 8), 256>>>(wo);
    k_red_out<<<(N_TOK * 2048 + 255) / 256, 256>>>(out);
}

// round 9
// speedup vs baseline: 3.1047x; 1.0186x over previous
#include <cuda_runtime.h>
#include <cuda_bf16.h>
#include <math.h>
#include <stdint.h>

// ---------------- problem constants ----------------
#define N_TOK   128
#define N_B     32
#define N_S     4
#define N_H     16
#define D_MODEL 2048
#define D_QL    1536
#define D_QB    3072
#define D_KVL   512
#define D_NOPE  128
#define D_ROPE  64
#define D_V     128
#define D_HD    192
#define T_MAX   8192
#define T_START 8188
#define KVPE    576
#define ATT_SCALE 0.07216878364870323f

#define BM 64
#define BN 128
#define BK 16
#define SR 24            // smem row stride (bf16) for 16-wide k tiles
#define BR 264           // smem row stride for attnout 256-col tiles
#define NSPLIT 8

typedef __nv_bfloat16 bf16;

// ---------------- static scratch ----------------
__device__ float g_t1[N_TOK * D_QL];
__device__ float g_q[N_TOK * D_QB];
__device__ float g_kvf[N_TOK * KVPE];
__device__ float g_kvnew[N_TOK * KVPE];
__device__ float g_qabs[N_B * 64 * KVPE];
__device__ bf16 g_qh[N_B * 64 * KVPE];
__device__ bf16 g_ql[N_B * 64 * KVPE];
__device__ bf16 g_Kh[(size_t)N_B * T_MAX * KVPE];
__device__ bf16 g_Kl[(size_t)N_B * T_MAX * KVPE];
__device__ bf16 g_Ph[(size_t)N_B * 64 * T_MAX];
__device__ bf16 g_Pl[(size_t)N_B * 64 * T_MAX];
__device__ float g_lp[N_B * 64 * 4 * 64];
__device__ float g_l[N_B * 64];
__device__ float g_part[(size_t)N_B * NSPLIT * 64 * D_KVL];
__device__ float g_attn[N_B * 64 * D_KVL];
__device__ float g_o[N_TOK * 2048];
__device__ float g_red[5000000];          // split-K partials (max 12*128*3072)

// ---------------- helpers ----------------
__device__ __forceinline__ uint32_t packbf2(bf16 a, bf16 b) {
    __nv_bfloat162 t = __halves2bfloat162(a, b);
    return *reinterpret_cast<uint32_t*>(&t);
}
__device__ __forceinline__ void split2(float a, float b, uint32_t& h, uint32_t& l) {
    bf16 ah = __float2bfloat16(a);
    bf16 bh = __float2bfloat16(b);
    bf16 al = __float2bfloat16(a - __bfloat162float(ah));
    bf16 bl = __float2bfloat16(b - __bfloat162float(bh));
    h = packbf2(ah, bh);
    l = packbf2(al, bl);
}
__device__ __forceinline__ void mma_bf16(float* c, const uint32_t* a, uint32_t b0, uint32_t b1) {
    asm volatile(
        "mma.sync.aligned.m16n8k16.row.col.f32.bf16.bf16.f32 "
        "{%0,%1,%2,%3}, {%4,%5,%6,%7}, {%8,%9}, {%0,%1,%2,%3};\n"
        : "+f"(c[0]), "+f"(c[1]), "+f"(c[2]), "+f"(c[3])
        : "r"(a[0]), "r"(a[1]), "r"(a[2]), "r"(a[3]), "r"(b0), "r"(b1));
}
__device__ __forceinline__ void cpa16(void* s, const void* g) {
    uint32_t sa = (uint32_t)__cvta_generic_to_shared(s);
    asm volatile("cp.async.cg.shared.global [%0], [%1], 16;\n" :: "r"(sa), "l"(g));
}
#define CP_COMMIT() asm volatile("cp.async.commit_group;\n")
#define CP_WAIT1()  asm volatile("cp.async.wait_group 1;\n")
#define CP_WAIT0()  asm volatile("cp.async.wait_group 0;\n")

__device__ __forceinline__ void ldsm4(uint32_t& r0, uint32_t& r1, uint32_t& r2, uint32_t& r3,
                                      const void* p) {
    uint32_t a = (uint32_t)__cvta_generic_to_shared(p);
    asm volatile("ldmatrix.sync.aligned.m8n8.x4.shared.b16 {%0,%1,%2,%3}, [%4];\n"
                 : "=r"(r0), "=r"(r1), "=r"(r2), "=r"(r3) : "r"(a));
}
__device__ __forceinline__ void ldsm4t(uint32_t& r0, uint32_t& r1, uint32_t& r2, uint32_t& r3,
                                       const void* p) {
    uint32_t a = (uint32_t)__cvta_generic_to_shared(p);
    asm volatile("ldmatrix.sync.aligned.m8n8.x4.trans.shared.b16 {%0,%1,%2,%3}, [%4];\n"
                 : "=r"(r0), "=r"(r1), "=r"(r2), "=r"(r3) : "r"(a));
}

// =======================================================================
// fp32 SGEMM NN body with K-range (for split-K). Tile 64x128, 256 thr.
// =======================================================================
__device__ __forceinline__ void sgemm_nn_body(
    const float* __restrict__ A, int lda,
    const float* __restrict__ B, int ldb,
    float* __restrict__ C, int ldc,
    int N, int kbeg, int kend)
{
    __shared__ float As[BK][BM];
    __shared__ float Bs[BK][BN];
    const int tid = threadIdx.x;
    const int tx = tid & 15, ty = tid >> 4;
    const int m0 = blockIdx.y * BM;
    const int n0 = blockIdx.x * BN;
    const int am = tid >> 2, ak = (tid & 3) << 2;
    const int bkr = tid >> 4, bn = (tid & 15) << 3;

    float acc[4][8];
#pragma unroll
    for (int i = 0; i < 4; i++)
#pragma unroll
        for (int j = 0; j < 8; j++) acc[i][j] = 0.f;

    for (int k0 = kbeg; k0 < kend; k0 += BK) {
        float4 av = *(const float4*)(A + (size_t)(m0 + am) * lda + k0 + ak);
        As[ak + 0][am] = av.x; As[ak + 1][am] = av.y;
        As[ak + 2][am] = av.z; As[ak + 3][am] = av.w;
        const float* bp = B + (size_t)(k0 + bkr) * ldb + n0 + bn;
        if (n0 + bn + 7 < N) {
            *(float4*)&Bs[bkr][bn]     = *(const float4*)bp;
            *(float4*)&Bs[bkr][bn + 4] = *(const float4*)(bp + 4);
        } else {
#pragma unroll
            for (int j = 0; j < 8; j++)
                Bs[bkr][bn + j] = (n0 + bn + j < N) ? bp[j] : 0.f;
        }
        __syncthreads();
#pragma unroll
        for (int kk = 0; kk < BK; kk++) {
            float a[4], bb[8];
            *(float4*)a      = *(const float4*)&As[kk][ty << 2];
            *(float4*)&bb[0] = *(const float4*)&Bs[kk][tx << 3];
            *(float4*)&bb[4] = *(const float4*)&Bs[kk][(tx << 3) + 4];
#pragma unroll
            for (int i = 0; i < 4; i++)
#pragma unroll
                for (int j = 0; j < 8; j++)
                    acc[i][j] = fmaf(a[i], bb[j], acc[i][j]);
        }
        __syncthreads();
    }
#pragma unroll
    for (int i = 0; i < 4; i++) {
        int m = m0 + (ty << 2) + i;
        float* cp = C + (size_t)m * ldc + n0 + (tx << 3);
#pragma unroll
        for (int j = 0; j < 8; j++)
            if (n0 + (tx << 3) + j < N) cp[j] = acc[i][j];
    }
}

// ---------------- split-K GEMM wrappers (higher split counts) ----------------
__global__ void k_sgemm_xqa(const float* __restrict__ x, const float* __restrict__ w) {
    const int z = blockIdx.z, ks = D_MODEL / 16;     // 16 splits
    sgemm_nn_body(x, D_MODEL, w, D_QL, g_red + (size_t)z * N_TOK * D_QL, D_QL,
                  D_QL, z * ks, (z + 1) * ks);
}
__global__ void k_sgemm_qb(const float* __restrict__ w) {
    const int z = blockIdx.z, ks = D_QL / 12;        // 12 splits
    sgemm_nn_body(g_t1, D_QL, w, D_QB, g_red + (size_t)z * N_TOK * D_QB, D_QB,
                  D_QB, z * ks, (z + 1) * ks);
}
__global__ void k_sgemm_kva(const float* __restrict__ x, const float* __restrict__ w) {
    const int z = blockIdx.z, ks = D_MODEL / 16;     // 16 splits
    sgemm_nn_body(x, D_MODEL, w, KVPE, g_red + (size_t)z * N_TOK * KVPE, KVPE,
                  KVPE, z * ks, (z + 1) * ks);
}
__global__ void k_sgemm_wo(const float* __restrict__ w) {
    const int z = blockIdx.z, ks = 2048 / 16;        // 16 splits
    sgemm_nn_body(g_o, 2048, w, 2048, g_red + (size_t)z * N_TOK * 2048, 2048,
                  2048, z * ks, (z + 1) * ks);
}

// ---------------- reduce wrappers ----------------
__device__ __forceinline__ void reduce_body(const float* __restrict__ src,
                                            float* __restrict__ dst, int mn, int splits) {
    int i = blockIdx.x * 256 + threadIdx.x;
    if (i >= mn) return;
    float s = 0.f;
    for (int k = 0; k < splits; k++) s += src[i + (size_t)k * mn];
    dst[i] = s;
}
__global__ void k_red_t1()  { reduce_body(g_red, g_t1,  N_TOK * D_QL, 16); }
__global__ void k_red_q()   { reduce_body(g_red, g_q,   N_TOK * D_QB, 12); }
__global__ void k_red_kvf() { reduce_body(g_red, g_kvf, N_TOK * KVPE, 16); }
__global__ void k_red_o()   { reduce_body(g_red, g_o,   N_TOK * 2048, 4); }
__global__ void k_red_out(float* __restrict__ out) { reduce_body(g_red, out, N_TOK * 2048, 16); }

// =======================================================================
// RMSNorm q_lora rows (1536)
// =======================================================================
__global__ void k_rms_q(const float* __restrict__ w)
{
    const int m = blockIdx.x, tid = threadIdx.x;
    float* row = g_t1 + (size_t)m * D_QL;
    float s = 0.f;
    for (int i = tid; i < D_QL / 4; i += 256) {
        float4 v = ((const float4*)row)[i];
        s += v.x * v.x + v.y * v.y + v.z * v.z + v.w * v.w;
    }
    __shared__ float sd[256];
    sd[tid] = s; __syncthreads();
    for (int o = 128; o > 0; o >>= 1) {
        if (tid < o) sd[tid] += sd[tid + o];
        __syncthreads();
    }
    const float inv = rsqrtf(sd[0] / (float)D_QL + 1e-6f);
    for (int i = tid; i < D_QL / 4; i += 256) {
        float4 v = ((const float4*)row)[i];
        float4 wv = ((const float4*)w)[i];
        v.x *= inv * wv.x; v.y *= inv * wv.y;
        v.z *= inv * wv.z; v.w *= inv * wv.w;
        ((float4*)row)[i] = v;
    }
}

// =======================================================================
// KV prep for the 4 new tokens per batch
// =======================================================================
__global__ void k_kvprep(const float* __restrict__ kvw,
                         const float* __restrict__ fc,
                         const float* __restrict__ fs)
{
    const int m = blockIdx.x, tid = threadIdx.x;
    const float* row = g_kvf + (size_t)m * KVPE;
    float* out = g_kvnew + (size_t)m * KVPE;
    float4 v = ((const float4*)row)[tid];
    float s = v.x * v.x + v.y * v.y + v.z * v.z + v.w * v.w;
    __shared__ float sd[128];
    sd[tid] = s; __syncthreads();
    for (int o = 64; o > 0; o >>= 1) {
        if (tid < o) sd[tid] += sd[tid + o];
        __syncthreads();
    }
    const float inv = rsqrtf(sd[0] / (float)D_KVL + 1e-6f);
    out[tid * 4 + 0] = v.x * inv * kvw[tid * 4 + 0];
    out[tid * 4 + 1] = v.y * inv * kvw[tid * 4 + 1];
    out[tid * 4 + 2] = v.z * inv * kvw[tid * 4 + 2];
    out[tid * 4 + 3] = v.w * inv * kvw[tid * 4 + 3];
    if (tid < 32) {
        const int sidx = m & 3;
        const float c = fc[sidx * 32 + tid], sn = fs[sidx * 32 + tid];
        const float x0 = row[512 + 2 * tid], x1 = row[512 + 2 * tid + 1];
        out[512 + 2 * tid]     = x0 * c - x1 * sn;
        out[512 + 2 * tid + 1] = x0 * sn + x1 * c;
    }
}

// =======================================================================
// Pre-convert full cache into bf16 hi/lo rows [b][t][576].
// =======================================================================
__global__ void k_cvt(const float* __restrict__ kvc, const float* __restrict__ pec)
{
    const uint32_t g = blockIdx.x * 256 + threadIdx.x;
    if (g >= (uint32_t)N_B * T_MAX * (KVPE / 8)) return;
    const uint32_t row = g / (KVPE / 8);
    const int seg = (g - row * (KVPE / 8)) * 8;
    const int t = row & (T_MAX - 1);
    const int b = row >> 13;

    const float* src;
    if (t >= T_START)       src = g_kvnew + (size_t)((b << 2) + (t - T_START)) * KVPE + seg;
    else if (seg < D_KVL)   src = kvc + (size_t)row * D_KVL + seg;
    else                    src = pec + (size_t)row * D_ROPE + (seg - D_KVL);

    float4 v0 = *(const float4*)src;
    float4 v1 = *(const float4*)(src + 4);
    uint32_t h[4], l[4];
    split2(v0.x, v0.y, h[0], l[0]);
    split2(v0.z, v0.w, h[1], l[1]);
    split2(v1.x, v1.y, h[2], l[2]);
    split2(v1.z, v1.w, h[3], l[3]);
    *(uint4*)(g_Kh + (size_t)row * KVPE + seg) = *(uint4*)h;
    *(uint4*)(g_Kl + (size_t)row * KVPE + seg) = *(uint4*)l;
}

// =======================================================================
// Absorb q_nope through wkv_b[:, :128, :] -> g_qabs[:, :512]
// =======================================================================
__global__ void k_absorb(const float* __restrict__ wkvb)
{
    __shared__ float As[BK][BM];
    __shared__ float Bs[BK][BN];
    const int h = blockIdx.z, tid = threadIdx.x;
    const int tx = tid & 15, ty = tid >> 4;
    const int m0 = blockIdx.y * BM, n0 = blockIdx.x * BN;
    const int am = tid >> 2, ak = (tid & 3) << 2;
    const int bkr = tid >> 4, bn = (tid & 15) << 3;
    const float* A = g_q + h * D_HD;
    const float* B = wkvb + (size_t)(h * 256) * D_KVL;
    float acc[4][8];
#pragma unroll
    for (int i = 0; i < 4; i++)
#pragma unroll
        for (int j = 0; j < 8; j++) acc[i][j] = 0.f;
    for (int k0 = 0; k0 < D_NOPE; k0 += BK) {
        float4 av = *(const float4*)(A + (size_t)(m0 + am) * D_QB + k0 + ak);
        As[ak + 0][am] = av.x; As[ak + 1][am] = av.y;
        As[ak + 2][am] = av.z; As[ak + 3][am] = av.w;
        const float* bp = B + (size_t)(k0 + bkr) * D_KVL + n0 + bn;
        *(float4*)&Bs[bkr][bn]     = *(const float4*)bp;
        *(float4*)&Bs[bkr][bn + 4] = *(const float4*)(bp + 4);
        __syncthreads();
#pragma unroll
        for (int kk = 0; kk < BK; kk++) {
            float a[4], bb[8];
            *(float4*)a      = *(const float4*)&As[kk][ty << 2];
            *(float4*)&bb[0] = *(const float4*)&Bs[kk][tx << 3];
            *(float4*)&bb[4] = *(const float4*)&Bs[kk][(tx << 3) + 4];
#pragma unroll
            for (int i = 0; i < 4; i++)
#pragma unroll
                for (int j = 0; j < 8; j++)
                    acc[i][j] = fmaf(a[i], bb[j], acc[i][j]);
        }
        __syncthreads();
    }
#pragma unroll
    for (int i = 0; i < 4; i++) {
        const int m = m0 + (ty << 2) + i;
        const int row = (m >> 2) * 64 + h * 4 + (m & 3);
        float* cp = g_qabs + (size_t)row * KVPE + n0 + (tx << 3);
#pragma unroll
        for (int j = 0; j < 8; j++) cp[j] = acc[i][j];
    }
}

// =======================================================================
// Rope q_pe -> g_qabs[..., 512:576]
// =======================================================================
__global__ void k_qrope(const float* __restrict__ fc, const float* __restrict__ fs)
{
    const int idx = blockIdx.x * blockDim.x + threadIdx.x;
    const int j = idx & 31, h = (idx >> 5) & 15, m = idx >> 9, s = m & 3;
    const float c = fc[s * 32 + j], sn = fs[s * 32 + j];
    const float* src = g_q + (size_t)m * D_QB + h * D_HD + D_NOPE + 2 * j;
    const float x0 = src[0], x1 = src[1];
    const int row = (m >> 2) * 64 + h * 4 + s;
    float* dst = g_qabs + (size_t)row * KVPE + 512 + 2 * j;
    dst[0] = x0 * c - x1 * sn;
    dst[1] = x0 * sn + x1 * c;
}

// =======================================================================
// Split g_qabs fp32 -> bf16 hi/lo
// =======================================================================
__global__ void k_qsplit()
{
    const int i = blockIdx.x * 256 + threadIdx.x;
    if (i >= N_B * 64 * KVPE) return;
    float v = g_qabs[i];
    bf16 h = __float2bfloat16(v);
    g_qh[i] = h;
    g_ql[i] = __float2bfloat16(v - __bfloat162float(h));
}

// =======================================================================
// Scores: P = exp(scale * Q' KV^T). (Round-4 proven)
// =======================================================================
__global__ __launch_bounds__(256, 2) void k_scores2()
{
    __shared__ bf16 Qh[2][64 * SR], Ql[2][64 * SR];
    __shared__ bf16 Kh[2][128 * SR], Kl[2][128 * SR];

    const int tid = threadIdx.x;
    const int lane = tid & 31, w = tid >> 5;
    const int wm = w & 1, wt = w >> 1;
    const int b = blockIdx.y;
    const int tt = blockIdx.x;
    const int t0 = tt * 128;

    float acc[2][4][4];
#pragma unroll
    for (int mi = 0; mi < 2; mi++)
#pragma unroll
        for (int ni = 0; ni < 4; ni++)
#pragma unroll
            for (int q = 0; q < 4; q++) acc[mi][ni][q] = 0.f;

    const int srow = tid >> 1, shf = (tid & 1) * 8;
    const bf16* gqh = g_qh + ((size_t)b * 64 + (srow & 63)) * KVPE + shf;
    const bf16* gql = g_ql + ((size_t)b * 64 + (srow & 63)) * KVPE + shf;
    const bf16* gkh = g_Kh + ((size_t)b * T_MAX + t0 + srow) * KVPE + shf;
    const bf16* gkl = g_Kl + ((size_t)b * T_MAX + t0 + srow) * KVPE + shf;

#define SC_STAGE(c, buf) do {                                             \
        const int k0_ = (c) * 16;                                         \
        if (tid < 128) {                                                  \
            cpa16(&Qh[buf][srow * SR + shf], gqh + k0_);                  \
            cpa16(&Ql[buf][srow * SR + shf], gql + k0_);                  \
        }                                                                 \
        cpa16(&Kh[buf][srow * SR + shf], gkh + k0_);                      \
        cpa16(&Kl[buf][srow * SR + shf], gkl + k0_);                      \
        CP_COMMIT();                                                      \
    } while (0)

    const int lg = lane >> 3, lidx = lane & 7;
    const int lr = lane >> 2, lk = (lane & 3) * 2;

    SC_STAGE(0, 0);

    for (int c = 0; c < KVPE / 16; c++) {
        const int buf = c & 1;
        if (c + 1 < KVPE / 16) SC_STAGE(c + 1, (c + 1) & 1);
        if (c + 1 < KVPE / 16) { CP_WAIT1(); } else { CP_WAIT0(); }
        __syncthreads();

        uint32_t ah[2][4], al[2][4];
#pragma unroll
        for (int mi = 0; mi < 2; mi++) {
            const int arow = wm * 32 + mi * 16 + ((lg & 1) << 3) + lidx;
            const int acol = (lg >> 1) << 3;
            ldsm4(ah[mi][0], ah[mi][1], ah[mi][2], ah[mi][3], &Qh[buf][arow * SR + acol]);
            ldsm4(al[mi][0], al[mi][1], al[mi][2], al[mi][3], &Ql[buf][arow * SR + acol]);
        }
#pragma unroll
        for (int p = 0; p < 2; p++) {
            const int brow = wt * 32 + p * 16 + ((lg >> 1) << 3) + lidx;
            const int bcol = (lg & 1) << 3;
            uint32_t bh[4], bl[4];
            ldsm4(bh[0], bh[1], bh[2], bh[3], &Kh[buf][brow * SR + bcol]);
            ldsm4(bl[0], bl[1], bl[2], bl[3], &Kl[buf][brow * SR + bcol]);
#pragma unroll
            for (int mi = 0; mi < 2; mi++) {
                mma_bf16(acc[mi][2 * p],     ah[mi], bh[0], bh[1]);
                mma_bf16(acc[mi][2 * p],     ah[mi], bl[0], bl[1]);
                mma_bf16(acc[mi][2 * p],     al[mi], bh[0], bh[1]);
                mma_bf16(acc[mi][2 * p + 1], ah[mi], bh[2], bh[3]);
                mma_bf16(acc[mi][2 * p + 1], ah[mi], bl[2], bl[3]);
                mma_bf16(acc[mi][2 * p + 1], al[mi], bh[2], bh[3]);
            }
        }
        __syncthreads();
    }
#undef SC_STAGE

    float s0[2] = {0.f, 0.f}, s1[2] = {0.f, 0.f};
#pragma unroll
    for (int mi = 0; mi < 2; mi++) {
#pragma unroll
        for (int ni = 0; ni < 4; ni++) {
            const int r = wm * 32 + mi * 16 + lr;
            const int t = t0 + wt * 32 + ni * 8 + lk;
            size_t base = ((size_t)b * 64 + r) * T_MAX + t;
            float e0 = __expf(acc[mi][ni][0] * ATT_SCALE);
            float e1 = __expf(acc[mi][ni][1] * ATT_SCALE);
            float e2 = __expf(acc[mi][ni][2] * ATT_SCALE);
            float e3 = __expf(acc[mi][ni][3] * ATT_SCALE);
            s0[mi] += e0 + e1;
            s1[mi] += e2 + e3;
            uint32_t h, l;
            split2(e0, e1, h, l);
            *(uint32_t*)&g_Ph[base] = h;
            *(uint32_t*)&g_Pl[base] = l;
            split2(e2, e3, h, l);
            *(uint32_t*)&g_Ph[base + (size_t)8 * T_MAX] = h;
            *(uint32_t*)&g_Pl[base + (size_t)8 * T_MAX] = l;
        }
    }
#pragma unroll
    for (int mi = 0; mi < 2; mi++) {
        s0[mi] += __shfl_xor_sync(0xffffffffu, s0[mi], 1);
        s0[mi] += __shfl_xor_sync(0xffffffffu, s0[mi], 2);
        s1[mi] += __shfl_xor_sync(0xffffffffu, s1[mi], 1);
        s1[mi] += __shfl_xor_sync(0xffffffffu, s1[mi], 2);
        if ((lane & 3) == 0) {
            const int r = wm * 32 + mi * 16 + lr;
            float* dst = g_lp + ((size_t)(b * 64 + tt) * 4 + wt) * 64;
            dst[r]     = s0[mi];
            dst[r + 8] = s1[mi];
        }
    }
}

__global__ void k_lred()
{
    const int b = blockIdx.x, r = threadIdx.x;
    float s = 0.f;
    for (int i = 0; i < 256; i++)
        s += g_lp[((size_t)(b * 64 + (i >> 2)) * 4 + (i & 3)) * 64 + r];
    g_l[b * 64 + r] = s;
}

// =======================================================================
// Attention out: partial = P @ KV over token slice. (Round-4 proven)
// =======================================================================
__global__ __launch_bounds__(256, 2) void k_attnout2()
{
    __shared__ bf16 Ah[2][64 * SR], Al[2][64 * SR];
    __shared__ bf16 Bh[2][16 * BR], Bl[2][16 * BR];

    const int tid = threadIdx.x;
    const int lane = tid & 31, w = tid >> 5;
    const int wm = w & 1, wc = w >> 1;
    const int c0 = blockIdx.x * 256;
    const int split = blockIdx.y;
    const int b = blockIdx.z;

    float acc[2][8][4];
#pragma unroll
    for (int mi = 0; mi < 2; mi++)
#pragma unroll
        for (int ni = 0; ni < 8; ni++)
#pragma unroll
            for (int q = 0; q < 4; q++) acc[mi][ni][q] = 0.f;

    const int arow = tid >> 1, ahf = (tid & 1) * 8;
    const int bt = tid >> 4, bcs = (tid & 15) * 16;
    const int tbase = split * (T_MAX / NSPLIT);

    const bf16* gph = g_Ph + ((size_t)b * 64 + (arow & 63)) * T_MAX + tbase + ahf;
    const bf16* gpl = g_Pl + ((size_t)b * 64 + (arow & 63)) * T_MAX + tbase + ahf;
    const bf16* gbh = g_Kh + ((size_t)b * T_MAX + tbase + bt) * KVPE + c0 + bcs;
    const bf16* gbl = g_Kl + ((size_t)b * T_MAX + tbase + bt) * KVPE + c0 + bcs;

#define AO_STAGE(c, buf) do {                                              \
        const int tk_ = (c) * 16;                                          \
        if (tid < 128) {                                                   \
            cpa16(&Ah[buf][arow * SR + ahf], gph + tk_);                   \
            cpa16(&Al[buf][arow * SR + ahf], gpl + tk_);                   \
        }                                                                  \
        cpa16(&Bh[buf][bt * BR + bcs],     gbh + (size_t)tk_ * KVPE);      \
        cpa16(&Bh[buf][bt * BR + bcs + 8], gbh + (size_t)tk_ * KVPE + 8);  \
        cpa16(&Bl[buf][bt * BR + bcs],     gbl + (size_t)tk_ * KVPE);      \
        cpa16(&Bl[buf][bt * BR + bcs + 8], gbl + (size_t)tk_ * KVPE + 8);  \
        CP_COMMIT();                                                       \
    } while (0)

    const int lg = lane >> 3, lidx = lane & 7;
    const int lr = lane >> 2, lk = (lane & 3) * 2;
    const int NCH = (T_MAX / NSPLIT) / 16;

    AO_STAGE(0, 0);

    for (int c = 0; c < NCH; c++) {
        const int buf = c & 1;
        if (c + 1 < NCH) AO_STAGE(c + 1, (c + 1) & 1);
        if (c + 1 < NCH) { CP_WAIT1(); } else { CP_WAIT0(); }
        __syncthreads();

        uint32_t ah[2][4], al[2][4];
#pragma unroll
        for (int mi = 0; mi < 2; mi++) {
            const int r = wm * 32 + mi * 16 + ((lg & 1) << 3) + lidx;
            const int acol = (lg >> 1) << 3;
            ldsm4(ah[mi][0], ah[mi][1], ah[mi][2], ah[mi][3], &Ah[buf][r * SR + acol]);
            ldsm4(al[mi][0], al[mi][1], al[mi][2], al[mi][3], &Al[buf][r * SR + acol]);
        }
#pragma unroll
        for (int p = 0; p < 4; p++) {
            const int C = wc * 64 + p * 16;
            const int brow = ((lg & 1) << 3) + lidx;
            const int bcol = C + ((lg >> 1) << 3);
            uint32_t bh[4], bl[4];
            ldsm4t(bh[0], bh[1], bh[2], bh[3], &Bh[buf][brow * BR + bcol]);
            ldsm4t(bl[0], bl[1], bl[2], bl[3], &Bl[buf][brow * BR + bcol]);
#pragma unroll
            for (int mi = 0; mi < 2; mi++) {
                mma_bf16(acc[mi][2 * p],     ah[mi], bh[0], bh[1]);
                mma_bf16(acc[mi][2 * p],     ah[mi], bl[0], bl[1]);
                mma_bf16(acc[mi][2 * p],     al[mi], bh[0], bh[1]);
                mma_bf16(acc[mi][2 * p + 1], ah[mi], bh[2], bh[3]);
                mma_bf16(acc[mi][2 * p + 1], ah[mi], bl[2], bl[3]);
                mma_bf16(acc[mi][2 * p + 1], al[mi], bh[2], bh[3]);
            }
        }
        __syncthreads();
    }
#undef AO_STAGE

#pragma unroll
    for (int mi = 0; mi < 2; mi++) {
#pragma unroll
        for (int ni = 0; ni < 8; ni++) {
            const int r = wm * 32 + mi * 16 + lr;
            const int cc = c0 + wc * 64 + ni * 8 + lk;
            float* p = g_part + (((size_t)(b * NSPLIT + split) * 64 + r) * D_KVL + cc);
            *(float2*)p = make_float2(acc[mi][ni][0], acc[mi][ni][1]);
            *(float2*)(p + (size_t)8 * D_KVL) = make_float2(acc[mi][ni][2], acc[mi][ni][3]);
        }
    }
}

// =======================================================================
// Reduce attn partials over splits and normalize by l.
// =======================================================================
__global__ void k_attnred()
{
    const int i = blockIdx.x * 256 + threadIdx.x;
    if (i >= N_B * 64 * D_KVL) return;
    const int c = i & 511;
    const int r = (i >> 9) & 63;
    const int b = i >> 15;
    float s = 0.f;
#pragma unroll
    for (int k = 0; k < NSPLIT; k++)
        s += g_part[((size_t)(b * NSPLIT + k) * 64 + r) * D_KVL + c];
    g_attn[((size_t)b * 64 + r) * D_KVL + c] = s / g_l[b * 64 + r];
}

// =======================================================================
// V projection, split-K over c (512 -> 4 x 128). grid (4 kz, 2 mtile, 16 h).
// =======================================================================
__global__ void k_projv(const float* __restrict__ wkvb)
{
    __shared__ float As[BK][BM];
    __shared__ float Bs[BK][BN];
    const int h = blockIdx.z, tid = threadIdx.x;
    const int kz = blockIdx.x;
    const int tx = tid & 15, ty = tid >> 4;
    const int m0 = blockIdx.y * BM;
    const int am = tid >> 2, ak = (tid & 3) << 2;
    const int bt = tid >> 1, bkq = (tid & 1) << 3;

    const int lm = m0 + am;
    const int arowi = (lm >> 2) * 64 + h * 4 + (lm & 3);
    const float* arp = g_attn + (size_t)arowi * D_KVL;
    const float* brp = wkvb + (size_t)(h * 256 + 128 + bt) * D_KVL;

    float acc[4][8];
#pragma unroll
    for (int i = 0; i < 4; i++)
#pragma unroll
        for (int j = 0; j < 8; j++) acc[i][j] = 0.f;

    const int kbeg = kz * 128, kend = kbeg + 128;
    for (int k0 = kbeg; k0 < kend; k0 += BK) {
        float4 av = *(const float4*)(arp + k0 + ak);
        As[ak + 0][am] = av.x; As[ak + 1][am] = av.y;
        As[ak + 2][am] = av.z; As[ak + 3][am] = av.w;
        float4 b0 = *(const float4*)(brp + k0 + bkq);
        float4 b1 = *(const float4*)(brp + k0 + bkq + 4);
        Bs[bkq + 0][bt] = b0.x; Bs[bkq + 1][bt] = b0.y;
        Bs[bkq + 2][bt] = b0.z; Bs[bkq + 3][bt] = b0.w;
        Bs[bkq + 4][bt] = b1.x; Bs[bkq + 5][bt] = b1.y;
        Bs[bkq + 6][bt] = b1.z; Bs[bkq + 7][bt] = b1.w;
        __syncthreads();
#pragma unroll
        for (int kk = 0; kk < BK; kk++) {
            float a[4], bb[8];
            *(float4*)a      = *(const float4*)&As[kk][ty << 2];
            *(float4*)&bb[0] = *(const float4*)&Bs[kk][tx << 3];
            *(float4*)&bb[4] = *(const float4*)&Bs[kk][(tx << 3) + 4];
#pragma unroll
            for (int i = 0; i < 4; i++)
#pragma unroll
                for (int j = 0; j < 8; j++)
                    acc[i][j] = fmaf(a[i], bb[j], acc[i][j]);
        }
        __syncthreads();
    }
#pragma unroll
    for (int i = 0; i < 4; i++) {
        const int m = m0 + (ty << 2) + i;
        float* cp = g_red + (size_t)kz * N_TOK * 2048 + (size_t)m * 2048 + h * D_V + (tx << 3);
#pragma unroll
        for (int j = 0; j < 8; j++) cp[j] = acc[i][j];
    }
}

// =======================================================================
// launch
// =======================================================================
extern "C" void kernel_launch(void* const* d_in, const int* in_sizes, int n_in,
                              void* d_out, int out_size)
{
    (void)in_sizes; (void)n_in; (void)out_size;
    const float* x     = (const float*)d_in[0];
    const float* wq_a  = (const float*)d_in[1];
    const float* qnw   = (const float*)d_in[2];
    const float* wq_b  = (const float*)d_in[3];
    const float* wkv_a = (const float*)d_in[4];
    const float* kvnw  = (const float*)d_in[5];
    const float* wkv_b = (const float*)d_in[6];
    const float* wo    = (const float*)d_in[7];
    const float* kvc   = (const float*)d_in[8];
    const float* pec   = (const float*)d_in[9];
    const float* fc    = (const float*)d_in[10];
    const float* fs    = (const float*)d_in[11];
    float* out = (float*)d_out;

    k_sgemm_xqa<<<dim3(D_QL / BN, 2, 16), 256>>>(x, wq_a);
    k_red_t1<<<(N_TOK * D_QL + 255) / 256, 256>>>();
    k_rms_q<<<N_TOK, 256>>>(qnw);
    k_sgemm_qb<<<dim3(D_QB / BN, 2, 12), 256>>>(wq_b);
    k_red_q<<<(N_TOK * D_QB + 255) / 256, 256>>>();
    k_sgemm_kva<<<dim3((KVPE + BN - 1) / BN, 2, 16), 256>>>(x, wkv_a);
    k_red_kvf<<<(N_TOK * KVPE + 255) / 256, 256>>>();
    k_kvprep<<<N_TOK, 128>>>(kvnw, fc, fs);
    k_cvt<<<(N_B * T_MAX * (KVPE / 8) + 255) / 256, 256>>>(kvc, pec);
    k_absorb<<<dim3(D_KVL / BN, 2, N_H), 256>>>(wkv_b);
    k_qrope<<<256, 256>>>(fc, fs);
    k_qsplit<<<(N_B * 64 * KVPE + 255) / 256, 256>>>();
    k_scores2<<<dim3(T_MAX / 128, N_B), 256>>>();
    k_lred<<<N_B, 64>>>();
    k_attnout2<<<dim3(2, NSPLIT, N_B), 256>>>();
    k_attnred<<<(N_B * 64 * D_KVL + 255) / 256, 256>>>();
    k_projv<<<dim3(4, 2, N_H), 256>>>(wkv_b);
    k_red_o<<<(N_TOK * 2048 + 255) / 256, 256>>>();
    k_sgemm_wo<<<dim3(2048 / BN, 2, 16), 256>>>(wo);
    k_red_out<<<(N_TOK * 2048 + 255) / 256, 256>>>(out);
}